// round 2
// baseline (speedup 1.0000x reference)
#include <cuda_runtime.h>
#include <math.h>

#define SEQ    4096
#define DIM    768
#define NH     12
#define HD     64
#define BATCH  2
#define MROWS  (BATCH*SEQ)    /* 8192 */
#define BHEADS (BATCH*NH)     /* 24   */

typedef unsigned long long ull;

// Scratch (no cudaMalloc allowed): q,k,v in [b,h,n,d]; attn out in [b,n,dim]
__device__ float g_q[(size_t)BHEADS*SEQ*HD];
__device__ float g_k[(size_t)BHEADS*SEQ*HD];
__device__ float g_v[(size_t)BHEADS*SEQ*HD];
__device__ float g_att[(size_t)MROWS*DIM];

// ---------------- packed f32x2 helpers -------------------------------------
__device__ __forceinline__ void fma2(ull& c, ull a, ull b) {
    asm("fma.rn.f32x2 %0, %1, %2, %0;" : "+l"(c) : "l"(a), "l"(b));
}
__device__ __forceinline__ void mul2(ull& c, ull a) {
    asm("mul.rn.f32x2 %0, %0, %1;" : "+l"(c) : "l"(a));
}
__device__ __forceinline__ ull pack2(float lo, float hi) {
    ull r; asm("mov.b64 %0, {%1, %2};" : "=l"(r) : "f"(lo), "f"(hi)); return r;
}
__device__ __forceinline__ void unpack2(float& lo, float& hi, ull p) {
    asm("mov.b64 {%0, %1}, %2;" : "=f"(lo), "=f"(hi) : "l"(p));
}
__device__ __forceinline__ float ex2f(float x) {
    float y; asm("ex2.approx.ftz.f32 %0, %1;" : "=f"(y) : "f"(x)); return y;
}

// scale = 64^-0.5 * log2(e), folded into Q at the QKV projection epilogue
#define QSCALE 0.18033688011112042f

// ---------------------------------------------------------------------------
// QKV projection: C = X @ W^T (blockIdx.z selects wq/wk/wv). 128x128 tile,
// 8x8 micro, K-chunk 16. A duplicated in smem (broadcast reads), B natural
// pairs -> inner loop is 32 FMA2 instead of 64 FFMA.
// ---------------------------------------------------------------------------
__global__ __launch_bounds__(256, 2)
void qkv_kernel(const float* __restrict__ x,
                const float* __restrict__ wq,
                const float* __restrict__ wk,
                const float* __restrict__ wv)
{
    __shared__ float AsTd[16][256];   // duplicated: AsTd[k][2r]=AsTd[k][2r+1]=A[m0+r][k]
    __shared__ float BsT [16][128];

    const float* W;
    float* out;
    float qs = 1.f;
    if (blockIdx.z == 0)      { W = wq; out = g_q; qs = QSCALE; }
    else if (blockIdx.z == 1) { W = wk; out = g_k; }
    else                      { W = wv; out = g_v; }

    const int tid  = threadIdx.x;
    const int m0   = blockIdx.x * 128;
    const int n0   = blockIdx.y * 128;
    const int lrow = tid >> 1;           // 0..127
    const int lk   = (tid & 1) * 8;      // 0 or 8
    const int ty   = tid >> 4;           // 0..15
    const int tx   = tid & 15;           // 0..15

    const float* ap = x + (size_t)(m0 + lrow) * DIM + lk;
    const float* bp = W + (size_t)(n0 + lrow) * DIM + lk;

    ull acc[8][4];
#pragma unroll
    for (int i = 0; i < 8; i++)
#pragma unroll
        for (int j = 0; j < 4; j++) acc[i][j] = 0ull;

    for (int kc = 0; kc < DIM; kc += 16) {
        float4 a0 = *(const float4*)(ap + kc);
        float4 a1 = *(const float4*)(ap + kc + 4);
        float4 b0 = *(const float4*)(bp + kc);
        float4 b1 = *(const float4*)(bp + kc + 4);
        __syncthreads();   // previous chunk's compute done
        *(float2*)&AsTd[lk+0][2*lrow] = make_float2(a0.x, a0.x);
        *(float2*)&AsTd[lk+1][2*lrow] = make_float2(a0.y, a0.y);
        *(float2*)&AsTd[lk+2][2*lrow] = make_float2(a0.z, a0.z);
        *(float2*)&AsTd[lk+3][2*lrow] = make_float2(a0.w, a0.w);
        *(float2*)&AsTd[lk+4][2*lrow] = make_float2(a1.x, a1.x);
        *(float2*)&AsTd[lk+5][2*lrow] = make_float2(a1.y, a1.y);
        *(float2*)&AsTd[lk+6][2*lrow] = make_float2(a1.z, a1.z);
        *(float2*)&AsTd[lk+7][2*lrow] = make_float2(a1.w, a1.w);
        BsT[lk+0][lrow] = b0.x; BsT[lk+1][lrow] = b0.y;
        BsT[lk+2][lrow] = b0.z; BsT[lk+3][lrow] = b0.w;
        BsT[lk+4][lrow] = b1.x; BsT[lk+5][lrow] = b1.y;
        BsT[lk+6][lrow] = b1.z; BsT[lk+7][lrow] = b1.w;
        __syncthreads();
#pragma unroll
        for (int kk = 0; kk < 16; kk++) {
            ulonglong2 aA = *(const ulonglong2*)&AsTd[kk][ty*16];
            ulonglong2 aB = *(const ulonglong2*)&AsTd[kk][ty*16+4];
            ulonglong2 aC = *(const ulonglong2*)&AsTd[kk][ty*16+8];
            ulonglong2 aD = *(const ulonglong2*)&AsTd[kk][ty*16+12];
            ulonglong2 bA = *(const ulonglong2*)&BsT[kk][tx*8];
            ulonglong2 bB = *(const ulonglong2*)&BsT[kk][tx*8+4];
            ull ad[8] = {aA.x, aA.y, aB.x, aB.y, aC.x, aC.y, aD.x, aD.y};
            ull bpr[4] = {bA.x, bA.y, bB.x, bB.y};
#pragma unroll
            for (int i = 0; i < 8; i++)
#pragma unroll
                for (int j = 0; j < 4; j++)
                    fma2(acc[i][j], ad[i], bpr[j]);
        }
    }

    // Store permuted to [b, h, n, d]  (cols n0 + tx*8 + 0..7)
#pragma unroll
    for (int i = 0; i < 8; i++) {
        int m = m0 + ty*8 + i;
        int b = m >> 12;            // /SEQ
        int n = m & (SEQ - 1);
        float c[8];
#pragma unroll
        for (int j = 0; j < 4; j++) {
            float lo, hi; unpack2(lo, hi, acc[i][j]);
            c[2*j] = lo * qs; c[2*j+1] = hi * qs;
        }
#pragma unroll
        for (int jj = 0; jj < 8; jj += 4) {
            int o    = n0 + tx*8 + jj;
            int head = o >> 6;
            int dc   = o & (HD - 1);
            *(float4*)(out + ((size_t)(b*NH + head)*SEQ + n)*HD + dc) =
                make_float4(c[jj], c[jj+1], c[jj+2], c[jj+3]);
        }
    }
}

// ---------------------------------------------------------------------------
// Flash attention with f32x2: 128 queries/block, KV tile 64, 256 threads.
// S = QK^T: Q natural row-pairs (pairs along q), K duplicated in smem.
// PV:       P transposed in smem (row-pairs natural), V duplicated.
// smem: QsT[64][132] KsTd[64][132] VsD[64][132] PsT[64][128] = 131 KB -> 1 CTA/SM
// ---------------------------------------------------------------------------
#define RP 132
__global__ __launch_bounds__(256)
void attn_kernel()
{
    extern __shared__ float sm[];
    float* QsT  = sm;              // [k][r]      64*132
    float* KsTd = sm + 64*RP;      // [k][2c dup] 64*132
    float* VsD  = sm + 2*64*RP;    // [kv][2d dup]64*132
    float* PsT  = sm + 3*64*RP;    // [kv][r swz] 64*128

    const int bh  = blockIdx.x;
    const int q0  = blockIdx.y * 128;
    const int tid = threadIdx.x;
    const int ty  = tid >> 4;        // 0..15
    const int tx  = tid & 15;        // 0..15
    const int r0  = ty * 8;

    const float* Qg = g_q + (size_t)bh * SEQ * HD;
    const float* Kg = g_k + (size_t)bh * SEQ * HD;
    const float* Vg = g_v + (size_t)bh * SEQ * HD;

    // Load Q tile transposed (scale already folded in at projection)
    {
        int r = tid >> 1;
        int ko = (tid & 1) * 32;
        const float* qp = Qg + (size_t)(q0 + r)*HD + ko;
#pragma unroll
        for (int u = 0; u < 32; u += 4) {
            float4 v = *(const float4*)(qp + u);
            QsT[(ko+u+0)*RP + r] = v.x;
            QsT[(ko+u+1)*RP + r] = v.y;
            QsT[(ko+u+2)*RP + r] = v.z;
            QsT[(ko+u+3)*RP + r] = v.w;
        }
    }

    float m_i[8], l_i[8];
    ull acc[4][4];                   // row-pairs (r0+2u, r0+2u+1) x 4 d-cols
#pragma unroll
    for (int i = 0; i < 8; i++) { m_i[i] = -INFINITY; l_i[i] = 0.f; }
#pragma unroll
    for (int u = 0; u < 4; u++)
#pragma unroll
        for (int j = 0; j < 4; j++) acc[u][j] = 0ull;

    const int rr = tid & 63;          // kv row within tile
    const int ko = (tid >> 6) * 16;   // k/d chunk

    for (int t = 0; t < SEQ/64; t++) {
        const int k0 = t * 64;
        const float* kp = Kg + (size_t)(k0 + rr)*HD + ko;
        const float* vp = Vg + (size_t)(k0 + rr)*HD + ko;
        float4 kr[4], vr[4];
#pragma unroll
        for (int e = 0; e < 4; e++) {
            kr[e] = *(const float4*)(kp + e*4);
            vr[e] = *(const float4*)(vp + e*4);
        }
        __syncthreads();   // previous tile's PV readers done
#pragma unroll
        for (int e = 0; e < 4; e++) {
            int kb = ko + e*4;
            *(float2*)&KsTd[(kb+0)*RP + 2*rr] = make_float2(kr[e].x, kr[e].x);
            *(float2*)&KsTd[(kb+1)*RP + 2*rr] = make_float2(kr[e].y, kr[e].y);
            *(float2*)&KsTd[(kb+2)*RP + 2*rr] = make_float2(kr[e].z, kr[e].z);
            *(float2*)&KsTd[(kb+3)*RP + 2*rr] = make_float2(kr[e].w, kr[e].w);
            *(float4*)&VsD[rr*RP + 2*kb]     = make_float4(vr[e].x, vr[e].x, vr[e].y, vr[e].y);
            *(float4*)&VsD[rr*RP + 2*kb + 4] = make_float4(vr[e].z, vr[e].z, vr[e].w, vr[e].w);
        }
        __syncthreads();

        // S = Q K^T : s2[u][j] = {S[r0+2u][c], S[r0+2u+1][c]}, c = tx*4+j
        ull s2[4][4];
#pragma unroll
        for (int u = 0; u < 4; u++)
#pragma unroll
            for (int j = 0; j < 4; j++) s2[u][j] = 0ull;

        const float* qrow = QsT + r0;
        const float* krow = KsTd + tx*8;
#pragma unroll 16
        for (int kk = 0; kk < 64; kk++) {
            ulonglong2 qA = *(const ulonglong2*)(qrow + kk*RP);
            ulonglong2 qB = *(const ulonglong2*)(qrow + kk*RP + 4);
            ulonglong2 kA = *(const ulonglong2*)(krow + kk*RP);
            ulonglong2 kB = *(const ulonglong2*)(krow + kk*RP + 4);
            ull qq[4] = {qA.x, qA.y, qB.x, qB.y};
            ull kd[4] = {kA.x, kA.y, kB.x, kB.y};
#pragma unroll
            for (int u = 0; u < 4; u++)
#pragma unroll
                for (int j = 0; j < 4; j++)
                    fma2(s2[u][j], qq[u], kd[j]);
        }

        // Online softmax (base 2) + store P transposed with XOR swizzle
#pragma unroll
        for (int u = 0; u < 4; u++) {
            float plo[4], phi[4];
#pragma unroll
            for (int j = 0; j < 4; j++) unpack2(plo[j], phi[j], s2[u][j]);

            float tl = fmaxf(fmaxf(plo[0], plo[1]), fmaxf(plo[2], plo[3]));
            float th = fmaxf(fmaxf(phi[0], phi[1]), fmaxf(phi[2], phi[3]));
#pragma unroll
            for (int off = 8; off > 0; off >>= 1) {
                tl = fmaxf(tl, __shfl_xor_sync(0xffffffffu, tl, off));
                th = fmaxf(th, __shfl_xor_sync(0xffffffffu, th, off));
            }
            float mnl = fmaxf(m_i[2*u],   tl);
            float mnh = fmaxf(m_i[2*u+1], th);
            float all = ex2f(m_i[2*u]   - mnl);
            float alh = ex2f(m_i[2*u+1] - mnh);
            float sl = 0.f, sh = 0.f;
#pragma unroll
            for (int j = 0; j < 4; j++) {
                plo[j] = ex2f(plo[j] - mnl); sl += plo[j];
                phi[j] = ex2f(phi[j] - mnh); sh += phi[j];
            }
#pragma unroll
            for (int off = 8; off > 0; off >>= 1) {
                sl += __shfl_xor_sync(0xffffffffu, sl, off);
                sh += __shfl_xor_sync(0xffffffffu, sh, off);
            }
            l_i[2*u]   = l_i[2*u]  * all + sl;  m_i[2*u]   = mnl;
            l_i[2*u+1] = l_i[2*u+1]* alh + sh;  m_i[2*u+1] = mnh;
            ull al2 = pack2(all, alh);
#pragma unroll
            for (int j = 0; j < 4; j++) mul2(acc[u][j], al2);

            int col = (r0 + 2*u) ^ (tx << 1);     // conflict-free swizzle
#pragma unroll
            for (int j = 0; j < 4; j++)
                *(float2*)&PsT[(tx*4+j)*128 + col] = make_float2(plo[j], phi[j]);
        }
        __syncthreads();

        // O += P V : acc[u][j] += {P[2u][kv],P[2u+1][kv]} * {V[kv][c],V[kv][c]}
        const float* vrow = VsD + tx*8;
#pragma unroll 2
        for (int g = 0; g < 16; g++) {
            int sw = g << 1;
            int c0 = (r0+0) ^ sw, c1 = (r0+2) ^ sw;
            int c2 = (r0+4) ^ sw, c3 = (r0+6) ^ sw;
            const float* pb = PsT + g*4*128;
#pragma unroll
            for (int q = 0; q < 4; q++) {
                ull p0 = *(const ull*)(pb + q*128 + c0);
                ull p1 = *(const ull*)(pb + q*128 + c1);
                ull p2 = *(const ull*)(pb + q*128 + c2);
                ull p3 = *(const ull*)(pb + q*128 + c3);
                ulonglong2 vA = *(const ulonglong2*)(vrow + (g*4+q)*RP);
                ulonglong2 vB = *(const ulonglong2*)(vrow + (g*4+q)*RP + 4);
                ull vd[4] = {vA.x, vA.y, vB.x, vB.y};
#pragma unroll
                for (int j = 0; j < 4; j++) {
                    fma2(acc[0][j], p0, vd[j]);
                    fma2(acc[1][j], p1, vd[j]);
                    fma2(acc[2][j], p2, vd[j]);
                    fma2(acc[3][j], p3, vd[j]);
                }
            }
        }
    }

    // Epilogue: normalize, unpack, store to [b, n, dim]
    const int b    = bh / NH;
    const int head = bh % NH;
    float* outp = g_att + ((size_t)b*SEQ + q0 + r0)*DIM + head*HD + tx*4;
#pragma unroll
    for (int u = 0; u < 4; u++) {
        float inl = 1.f / l_i[2*u];
        float inh = 1.f / l_i[2*u+1];
        float ol[4], oh[4];
#pragma unroll
        for (int j = 0; j < 4; j++) unpack2(ol[j], oh[j], acc[u][j]);
        *(float4*)(outp + (size_t)(2*u)*DIM) =
            make_float4(ol[0]*inl, ol[1]*inl, ol[2]*inl, ol[3]*inl);
        *(float4*)(outp + (size_t)(2*u+1)*DIM) =
            make_float4(oh[0]*inh, oh[1]*inh, oh[2]*inh, oh[3]*inh);
    }
}

// ---------------------------------------------------------------------------
// Output projection: d_out = g_att @ wo^T + bo   (same FMA2 GEMM scheme)
// ---------------------------------------------------------------------------
__global__ __launch_bounds__(256, 2)
void proj_kernel(const float* __restrict__ wo,
                 const float* __restrict__ bo,
                 float* __restrict__ out)
{
    __shared__ float AsTd[16][256];
    __shared__ float BsT [16][128];

    const int tid  = threadIdx.x;
    const int m0   = blockIdx.x * 128;
    const int n0   = blockIdx.y * 128;
    const int lrow = tid >> 1;
    const int lk   = (tid & 1) * 8;
    const int ty   = tid >> 4;
    const int tx   = tid & 15;

    const float* ap = g_att + (size_t)(m0 + lrow) * DIM + lk;
    const float* bp = wo    + (size_t)(n0 + lrow) * DIM + lk;

    ull acc[8][4];
#pragma unroll
    for (int i = 0; i < 8; i++)
#pragma unroll
        for (int j = 0; j < 4; j++) acc[i][j] = 0ull;

    for (int kc = 0; kc < DIM; kc += 16) {
        float4 a0 = *(const float4*)(ap + kc);
        float4 a1 = *(const float4*)(ap + kc + 4);
        float4 b0 = *(const float4*)(bp + kc);
        float4 b1 = *(const float4*)(bp + kc + 4);
        __syncthreads();
        *(float2*)&AsTd[lk+0][2*lrow] = make_float2(a0.x, a0.x);
        *(float2*)&AsTd[lk+1][2*lrow] = make_float2(a0.y, a0.y);
        *(float2*)&AsTd[lk+2][2*lrow] = make_float2(a0.z, a0.z);
        *(float2*)&AsTd[lk+3][2*lrow] = make_float2(a0.w, a0.w);
        *(float2*)&AsTd[lk+4][2*lrow] = make_float2(a1.x, a1.x);
        *(float2*)&AsTd[lk+5][2*lrow] = make_float2(a1.y, a1.y);
        *(float2*)&AsTd[lk+6][2*lrow] = make_float2(a1.z, a1.z);
        *(float2*)&AsTd[lk+7][2*lrow] = make_float2(a1.w, a1.w);
        BsT[lk+0][lrow] = b0.x; BsT[lk+1][lrow] = b0.y;
        BsT[lk+2][lrow] = b0.z; BsT[lk+3][lrow] = b0.w;
        BsT[lk+4][lrow] = b1.x; BsT[lk+5][lrow] = b1.y;
        BsT[lk+6][lrow] = b1.z; BsT[lk+7][lrow] = b1.w;
        __syncthreads();
#pragma unroll
        for (int kk = 0; kk < 16; kk++) {
            ulonglong2 aA = *(const ulonglong2*)&AsTd[kk][ty*16];
            ulonglong2 aB = *(const ulonglong2*)&AsTd[kk][ty*16+4];
            ulonglong2 aC = *(const ulonglong2*)&AsTd[kk][ty*16+8];
            ulonglong2 aD = *(const ulonglong2*)&AsTd[kk][ty*16+12];
            ulonglong2 bA = *(const ulonglong2*)&BsT[kk][tx*8];
            ulonglong2 bB = *(const ulonglong2*)&BsT[kk][tx*8+4];
            ull ad[8] = {aA.x, aA.y, aB.x, aB.y, aC.x, aC.y, aD.x, aD.y};
            ull bpr[4] = {bA.x, bA.y, bB.x, bB.y};
#pragma unroll
            for (int i = 0; i < 8; i++)
#pragma unroll
                for (int j = 0; j < 4; j++)
                    fma2(acc[i][j], ad[i], bpr[j]);
        }
    }

#pragma unroll
    for (int i = 0; i < 8; i++) {
        int m = m0 + ty*8 + i;
        float c[8];
#pragma unroll
        for (int j = 0; j < 4; j++) {
            float lo, hi; unpack2(lo, hi, acc[i][j]);
            c[2*j] = lo; c[2*j+1] = hi;
        }
#pragma unroll
        for (int jj = 0; jj < 8; jj += 4) {
            int o = n0 + tx*8 + jj;
            float4 bb = *(const float4*)(bo + o);
            *(float4*)(out + (size_t)m*DIM + o) =
                make_float4(c[jj]+bb.x, c[jj+1]+bb.y, c[jj+2]+bb.z, c[jj+3]+bb.w);
        }
    }
}

// ---------------------------------------------------------------------------
extern "C" void kernel_launch(void* const* d_in, const int* in_sizes, int n_in,
                              void* d_out, int out_size)
{
    const float* x  = (const float*)d_in[0];
    const float* wq = (const float*)d_in[1];
    const float* wk = (const float*)d_in[2];
    const float* wv = (const float*)d_in[3];
    const float* wo = (const float*)d_in[4];
    const float* bo = (const float*)d_in[5];
    float* out = (float*)d_out;

    (void)in_sizes; (void)n_in; (void)out_size;

    const int attn_smem = (3*64*RP + 64*128) * 4;   // 134144 B
    cudaFuncSetAttribute(attn_kernel,
                         cudaFuncAttributeMaxDynamicSharedMemorySize, attn_smem);

    qkv_kernel<<<dim3(MROWS/128, DIM/128, 3), 256>>>(x, wq, wk, wv);
    attn_kernel<<<dim3(BHEADS, SEQ/128), 256, attn_smem>>>();
    proj_kernel<<<dim3(MROWS/128, DIM/128), 256>>>(wo, bo, out);
}

// round 3
// speedup vs baseline: 1.0007x; 1.0007x over previous
#include <cuda_runtime.h>
#include <math.h>

#define SEQ    4096
#define DIM    768
#define NH     12
#define HD     64
#define BATCH  2
#define MROWS  (BATCH*SEQ)    /* 8192 */
#define BHEADS (BATCH*NH)     /* 24   */

typedef unsigned long long ull;

// Scratch (no cudaMalloc allowed): q,k,v in [b,h,n,d]; attn out in [b,n,dim]
__device__ float g_q[(size_t)BHEADS*SEQ*HD];
__device__ float g_k[(size_t)BHEADS*SEQ*HD];
__device__ float g_v[(size_t)BHEADS*SEQ*HD];
__device__ float g_att[(size_t)MROWS*DIM];

// ---------------- packed f32x2 helpers -------------------------------------
__device__ __forceinline__ void fma2(ull& c, ull a, ull b) {
    asm("fma.rn.f32x2 %0, %1, %2, %0;" : "+l"(c) : "l"(a), "l"(b));
}
__device__ __forceinline__ void mul2(ull& c, ull a) {
    asm("mul.rn.f32x2 %0, %0, %1;" : "+l"(c) : "l"(a));
}
__device__ __forceinline__ ull pack2(float lo, float hi) {
    ull r; asm("mov.b64 %0, {%1, %2};" : "=l"(r) : "f"(lo), "f"(hi)); return r;
}
__device__ __forceinline__ void unpack2(float& lo, float& hi, ull p) {
    asm("mov.b64 {%0, %1}, %2;" : "=f"(lo), "=f"(hi) : "l"(p));
}
__device__ __forceinline__ float ex2f(float x) {
    float y; asm("ex2.approx.ftz.f32 %0, %1;" : "=f"(y) : "f"(x)); return y;
}

// scale = 64^-0.5 * log2(e), folded into Q at the QKV projection epilogue
#define QSCALE 0.18033688011112042f

// ---------------------------------------------------------------------------
// QKV projection: C = X @ W^T (blockIdx.z selects wq/wk/wv). 128x128 tile,
// 8x8 micro, K-chunk 16. A duplicated in smem (broadcast reads), B natural
// pairs -> inner loop is 32 FMA2 instead of 64 FFMA.
// ---------------------------------------------------------------------------
__global__ __launch_bounds__(256, 2)
void qkv_kernel(const float* __restrict__ x,
                const float* __restrict__ wq,
                const float* __restrict__ wk,
                const float* __restrict__ wv)
{
    __shared__ float AsTd[16][256];   // duplicated: AsTd[k][2r]=AsTd[k][2r+1]=A[m0+r][k]
    __shared__ float BsT [16][128];

    const float* W;
    float* out;
    float qs = 1.f;
    if (blockIdx.z == 0)      { W = wq; out = g_q; qs = QSCALE; }
    else if (blockIdx.z == 1) { W = wk; out = g_k; }
    else                      { W = wv; out = g_v; }

    const int tid  = threadIdx.x;
    const int m0   = blockIdx.x * 128;
    const int n0   = blockIdx.y * 128;
    const int lrow = tid >> 1;           // 0..127
    const int lk   = (tid & 1) * 8;      // 0 or 8
    const int ty   = tid >> 4;           // 0..15
    const int tx   = tid & 15;           // 0..15

    const float* ap = x + (size_t)(m0 + lrow) * DIM + lk;
    const float* bp = W + (size_t)(n0 + lrow) * DIM + lk;

    ull acc[8][4];
#pragma unroll
    for (int i = 0; i < 8; i++)
#pragma unroll
        for (int j = 0; j < 4; j++) acc[i][j] = 0ull;

    for (int kc = 0; kc < DIM; kc += 16) {
        float4 a0 = *(const float4*)(ap + kc);
        float4 a1 = *(const float4*)(ap + kc + 4);
        float4 b0 = *(const float4*)(bp + kc);
        float4 b1 = *(const float4*)(bp + kc + 4);
        __syncthreads();   // previous chunk's compute done
        *(float2*)&AsTd[lk+0][2*lrow] = make_float2(a0.x, a0.x);
        *(float2*)&AsTd[lk+1][2*lrow] = make_float2(a0.y, a0.y);
        *(float2*)&AsTd[lk+2][2*lrow] = make_float2(a0.z, a0.z);
        *(float2*)&AsTd[lk+3][2*lrow] = make_float2(a0.w, a0.w);
        *(float2*)&AsTd[lk+4][2*lrow] = make_float2(a1.x, a1.x);
        *(float2*)&AsTd[lk+5][2*lrow] = make_float2(a1.y, a1.y);
        *(float2*)&AsTd[lk+6][2*lrow] = make_float2(a1.z, a1.z);
        *(float2*)&AsTd[lk+7][2*lrow] = make_float2(a1.w, a1.w);
        BsT[lk+0][lrow] = b0.x; BsT[lk+1][lrow] = b0.y;
        BsT[lk+2][lrow] = b0.z; BsT[lk+3][lrow] = b0.w;
        BsT[lk+4][lrow] = b1.x; BsT[lk+5][lrow] = b1.y;
        BsT[lk+6][lrow] = b1.z; BsT[lk+7][lrow] = b1.w;
        __syncthreads();
#pragma unroll
        for (int kk = 0; kk < 16; kk++) {
            ulonglong2 aA = *(const ulonglong2*)&AsTd[kk][ty*16];
            ulonglong2 aB = *(const ulonglong2*)&AsTd[kk][ty*16+4];
            ulonglong2 aC = *(const ulonglong2*)&AsTd[kk][ty*16+8];
            ulonglong2 aD = *(const ulonglong2*)&AsTd[kk][ty*16+12];
            ulonglong2 bA = *(const ulonglong2*)&BsT[kk][tx*8];
            ulonglong2 bB = *(const ulonglong2*)&BsT[kk][tx*8+4];
            ull ad[8] = {aA.x, aA.y, aB.x, aB.y, aC.x, aC.y, aD.x, aD.y};
            ull bpr[4] = {bA.x, bA.y, bB.x, bB.y};
#pragma unroll
            for (int i = 0; i < 8; i++)
#pragma unroll
                for (int j = 0; j < 4; j++)
                    fma2(acc[i][j], ad[i], bpr[j]);
        }
    }

    // Store permuted to [b, h, n, d]  (cols n0 + tx*8 + 0..7)
#pragma unroll
    for (int i = 0; i < 8; i++) {
        int m = m0 + ty*8 + i;
        int b = m >> 12;            // /SEQ
        int n = m & (SEQ - 1);
        float c[8];
#pragma unroll
        for (int j = 0; j < 4; j++) {
            float lo, hi; unpack2(lo, hi, acc[i][j]);
            c[2*j] = lo * qs; c[2*j+1] = hi * qs;
        }
#pragma unroll
        for (int jj = 0; jj < 8; jj += 4) {
            int o    = n0 + tx*8 + jj;
            int head = o >> 6;
            int dc   = o & (HD - 1);
            *(float4*)(out + ((size_t)(b*NH + head)*SEQ + n)*HD + dc) =
                make_float4(c[jj], c[jj+1], c[jj+2], c[jj+3]);
        }
    }
}

// ---------------------------------------------------------------------------
// Flash attention with f32x2: 128 queries/block, KV tile 64, 256 threads.
// S = QK^T: Q natural row-pairs (pairs along q), K duplicated in smem.
// PV:       P transposed in smem (row-pairs natural), V duplicated.
// smem: QsT[64][132] KsTd[64][132] VsD[64][132] PsT[64][128] = 131 KB -> 1 CTA/SM
// ---------------------------------------------------------------------------
#define RP 132
__global__ __launch_bounds__(256)
void attn_kernel()
{
    extern __shared__ float sm[];
    float* QsT  = sm;              // [k][r]      64*132
    float* KsTd = sm + 64*RP;      // [k][2c dup] 64*132
    float* VsD  = sm + 2*64*RP;    // [kv][2d dup]64*132
    float* PsT  = sm + 3*64*RP;    // [kv][r swz] 64*128

    const int bh  = blockIdx.x;
    const int q0  = blockIdx.y * 128;
    const int tid = threadIdx.x;
    const int ty  = tid >> 4;        // 0..15
    const int tx  = tid & 15;        // 0..15
    const int r0  = ty * 8;

    const float* Qg = g_q + (size_t)bh * SEQ * HD;
    const float* Kg = g_k + (size_t)bh * SEQ * HD;
    const float* Vg = g_v + (size_t)bh * SEQ * HD;

    // Load Q tile transposed (scale already folded in at projection)
    {
        int r = tid >> 1;
        int ko = (tid & 1) * 32;
        const float* qp = Qg + (size_t)(q0 + r)*HD + ko;
#pragma unroll
        for (int u = 0; u < 32; u += 4) {
            float4 v = *(const float4*)(qp + u);
            QsT[(ko+u+0)*RP + r] = v.x;
            QsT[(ko+u+1)*RP + r] = v.y;
            QsT[(ko+u+2)*RP + r] = v.z;
            QsT[(ko+u+3)*RP + r] = v.w;
        }
    }

    float m_i[8], l_i[8];
    ull acc[4][4];                   // row-pairs (r0+2u, r0+2u+1) x 4 d-cols
#pragma unroll
    for (int i = 0; i < 8; i++) { m_i[i] = -INFINITY; l_i[i] = 0.f; }
#pragma unroll
    for (int u = 0; u < 4; u++)
#pragma unroll
        for (int j = 0; j < 4; j++) acc[u][j] = 0ull;

    const int rr = tid & 63;          // kv row within tile
    const int ko = (tid >> 6) * 16;   // k/d chunk

    for (int t = 0; t < SEQ/64; t++) {
        const int k0 = t * 64;
        const float* kp = Kg + (size_t)(k0 + rr)*HD + ko;
        const float* vp = Vg + (size_t)(k0 + rr)*HD + ko;
        float4 kr[4], vr[4];
#pragma unroll
        for (int e = 0; e < 4; e++) {
            kr[e] = *(const float4*)(kp + e*4);
            vr[e] = *(const float4*)(vp + e*4);
        }
        __syncthreads();   // previous tile's PV readers done
#pragma unroll
        for (int e = 0; e < 4; e++) {
            int kb = ko + e*4;
            *(float2*)&KsTd[(kb+0)*RP + 2*rr] = make_float2(kr[e].x, kr[e].x);
            *(float2*)&KsTd[(kb+1)*RP + 2*rr] = make_float2(kr[e].y, kr[e].y);
            *(float2*)&KsTd[(kb+2)*RP + 2*rr] = make_float2(kr[e].z, kr[e].z);
            *(float2*)&KsTd[(kb+3)*RP + 2*rr] = make_float2(kr[e].w, kr[e].w);
            *(float4*)&VsD[rr*RP + 2*kb]     = make_float4(vr[e].x, vr[e].x, vr[e].y, vr[e].y);
            *(float4*)&VsD[rr*RP + 2*kb + 4] = make_float4(vr[e].z, vr[e].z, vr[e].w, vr[e].w);
        }
        __syncthreads();

        // S = Q K^T : s2[u][j] = {S[r0+2u][c], S[r0+2u+1][c]}, c = tx*4+j
        ull s2[4][4];
#pragma unroll
        for (int u = 0; u < 4; u++)
#pragma unroll
            for (int j = 0; j < 4; j++) s2[u][j] = 0ull;

        const float* qrow = QsT + r0;
        const float* krow = KsTd + tx*8;
#pragma unroll 16
        for (int kk = 0; kk < 64; kk++) {
            ulonglong2 qA = *(const ulonglong2*)(qrow + kk*RP);
            ulonglong2 qB = *(const ulonglong2*)(qrow + kk*RP + 4);
            ulonglong2 kA = *(const ulonglong2*)(krow + kk*RP);
            ulonglong2 kB = *(const ulonglong2*)(krow + kk*RP + 4);
            ull qq[4] = {qA.x, qA.y, qB.x, qB.y};
            ull kd[4] = {kA.x, kA.y, kB.x, kB.y};
#pragma unroll
            for (int u = 0; u < 4; u++)
#pragma unroll
                for (int j = 0; j < 4; j++)
                    fma2(s2[u][j], qq[u], kd[j]);
        }

        // Online softmax (base 2) + store P transposed with XOR swizzle
#pragma unroll
        for (int u = 0; u < 4; u++) {
            float plo[4], phi[4];
#pragma unroll
            for (int j = 0; j < 4; j++) unpack2(plo[j], phi[j], s2[u][j]);

            float tl = fmaxf(fmaxf(plo[0], plo[1]), fmaxf(plo[2], plo[3]));
            float th = fmaxf(fmaxf(phi[0], phi[1]), fmaxf(phi[2], phi[3]));
#pragma unroll
            for (int off = 8; off > 0; off >>= 1) {
                tl = fmaxf(tl, __shfl_xor_sync(0xffffffffu, tl, off));
                th = fmaxf(th, __shfl_xor_sync(0xffffffffu, th, off));
            }
            float mnl = fmaxf(m_i[2*u],   tl);
            float mnh = fmaxf(m_i[2*u+1], th);
            float all = ex2f(m_i[2*u]   - mnl);
            float alh = ex2f(m_i[2*u+1] - mnh);
            float sl = 0.f, sh = 0.f;
#pragma unroll
            for (int j = 0; j < 4; j++) {
                plo[j] = ex2f(plo[j] - mnl); sl += plo[j];
                phi[j] = ex2f(phi[j] - mnh); sh += phi[j];
            }
#pragma unroll
            for (int off = 8; off > 0; off >>= 1) {
                sl += __shfl_xor_sync(0xffffffffu, sl, off);
                sh += __shfl_xor_sync(0xffffffffu, sh, off);
            }
            l_i[2*u]   = l_i[2*u]  * all + sl;  m_i[2*u]   = mnl;
            l_i[2*u+1] = l_i[2*u+1]* alh + sh;  m_i[2*u+1] = mnh;
            ull al2 = pack2(all, alh);
#pragma unroll
            for (int j = 0; j < 4; j++) mul2(acc[u][j], al2);

            int col = (r0 + 2*u) ^ (tx << 1);     // conflict-free swizzle
#pragma unroll
            for (int j = 0; j < 4; j++)
                *(float2*)&PsT[(tx*4+j)*128 + col] = make_float2(plo[j], phi[j]);
        }
        __syncthreads();

        // O += P V : acc[u][j] += {P[2u][kv],P[2u+1][kv]} * {V[kv][c],V[kv][c]}
        const float* vrow = VsD + tx*8;
#pragma unroll 2
        for (int g = 0; g < 16; g++) {
            int sw = g << 1;
            int c0 = (r0+0) ^ sw, c1 = (r0+2) ^ sw;
            int c2 = (r0+4) ^ sw, c3 = (r0+6) ^ sw;
            const float* pb = PsT + g*4*128;
#pragma unroll
            for (int q = 0; q < 4; q++) {
                ull p0 = *(const ull*)(pb + q*128 + c0);
                ull p1 = *(const ull*)(pb + q*128 + c1);
                ull p2 = *(const ull*)(pb + q*128 + c2);
                ull p3 = *(const ull*)(pb + q*128 + c3);
                ulonglong2 vA = *(const ulonglong2*)(vrow + (g*4+q)*RP);
                ulonglong2 vB = *(const ulonglong2*)(vrow + (g*4+q)*RP + 4);
                ull vd[4] = {vA.x, vA.y, vB.x, vB.y};
#pragma unroll
                for (int j = 0; j < 4; j++) {
                    fma2(acc[0][j], p0, vd[j]);
                    fma2(acc[1][j], p1, vd[j]);
                    fma2(acc[2][j], p2, vd[j]);
                    fma2(acc[3][j], p3, vd[j]);
                }
            }
        }
    }

    // Epilogue: normalize, unpack, store to [b, n, dim]
    const int b    = bh / NH;
    const int head = bh % NH;
    float* outp = g_att + ((size_t)b*SEQ + q0 + r0)*DIM + head*HD + tx*4;
#pragma unroll
    for (int u = 0; u < 4; u++) {
        float inl = 1.f / l_i[2*u];
        float inh = 1.f / l_i[2*u+1];
        float ol[4], oh[4];
#pragma unroll
        for (int j = 0; j < 4; j++) unpack2(ol[j], oh[j], acc[u][j]);
        *(float4*)(outp + (size_t)(2*u)*DIM) =
            make_float4(ol[0]*inl, ol[1]*inl, ol[2]*inl, ol[3]*inl);
        *(float4*)(outp + (size_t)(2*u+1)*DIM) =
            make_float4(oh[0]*inh, oh[1]*inh, oh[2]*inh, oh[3]*inh);
    }
}

// ---------------------------------------------------------------------------
// Output projection: d_out = g_att @ wo^T + bo   (same FMA2 GEMM scheme)
// ---------------------------------------------------------------------------
__global__ __launch_bounds__(256, 2)
void proj_kernel(const float* __restrict__ wo,
                 const float* __restrict__ bo,
                 float* __restrict__ out)
{
    __shared__ float AsTd[16][256];
    __shared__ float BsT [16][128];

    const int tid  = threadIdx.x;
    const int m0   = blockIdx.x * 128;
    const int n0   = blockIdx.y * 128;
    const int lrow = tid >> 1;
    const int lk   = (tid & 1) * 8;
    const int ty   = tid >> 4;
    const int tx   = tid & 15;

    const float* ap = g_att + (size_t)(m0 + lrow) * DIM + lk;
    const float* bp = wo    + (size_t)(n0 + lrow) * DIM + lk;

    ull acc[8][4];
#pragma unroll
    for (int i = 0; i < 8; i++)
#pragma unroll
        for (int j = 0; j < 4; j++) acc[i][j] = 0ull;

    for (int kc = 0; kc < DIM; kc += 16) {
        float4 a0 = *(const float4*)(ap + kc);
        float4 a1 = *(const float4*)(ap + kc + 4);
        float4 b0 = *(const float4*)(bp + kc);
        float4 b1 = *(const float4*)(bp + kc + 4);
        __syncthreads();
        *(float2*)&AsTd[lk+0][2*lrow] = make_float2(a0.x, a0.x);
        *(float2*)&AsTd[lk+1][2*lrow] = make_float2(a0.y, a0.y);
        *(float2*)&AsTd[lk+2][2*lrow] = make_float2(a0.z, a0.z);
        *(float2*)&AsTd[lk+3][2*lrow] = make_float2(a0.w, a0.w);
        *(float2*)&AsTd[lk+4][2*lrow] = make_float2(a1.x, a1.x);
        *(float2*)&AsTd[lk+5][2*lrow] = make_float2(a1.y, a1.y);
        *(float2*)&AsTd[lk+6][2*lrow] = make_float2(a1.z, a1.z);
        *(float2*)&AsTd[lk+7][2*lrow] = make_float2(a1.w, a1.w);
        BsT[lk+0][lrow] = b0.x; BsT[lk+1][lrow] = b0.y;
        BsT[lk+2][lrow] = b0.z; BsT[lk+3][lrow] = b0.w;
        BsT[lk+4][lrow] = b1.x; BsT[lk+5][lrow] = b1.y;
        BsT[lk+6][lrow] = b1.z; BsT[lk+7][lrow] = b1.w;
        __syncthreads();
#pragma unroll
        for (int kk = 0; kk < 16; kk++) {
            ulonglong2 aA = *(const ulonglong2*)&AsTd[kk][ty*16];
            ulonglong2 aB = *(const ulonglong2*)&AsTd[kk][ty*16+4];
            ulonglong2 aC = *(const ulonglong2*)&AsTd[kk][ty*16+8];
            ulonglong2 aD = *(const ulonglong2*)&AsTd[kk][ty*16+12];
            ulonglong2 bA = *(const ulonglong2*)&BsT[kk][tx*8];
            ulonglong2 bB = *(const ulonglong2*)&BsT[kk][tx*8+4];
            ull ad[8] = {aA.x, aA.y, aB.x, aB.y, aC.x, aC.y, aD.x, aD.y};
            ull bpr[4] = {bA.x, bA.y, bB.x, bB.y};
#pragma unroll
            for (int i = 0; i < 8; i++)
#pragma unroll
                for (int j = 0; j < 4; j++)
                    fma2(acc[i][j], ad[i], bpr[j]);
        }
    }

#pragma unroll
    for (int i = 0; i < 8; i++) {
        int m = m0 + ty*8 + i;
        float c[8];
#pragma unroll
        for (int j = 0; j < 4; j++) {
            float lo, hi; unpack2(lo, hi, acc[i][j]);
            c[2*j] = lo; c[2*j+1] = hi;
        }
#pragma unroll
        for (int jj = 0; jj < 8; jj += 4) {
            int o = n0 + tx*8 + jj;
            float4 bb = *(const float4*)(bo + o);
            *(float4*)(out + (size_t)m*DIM + o) =
                make_float4(c[jj]+bb.x, c[jj+1]+bb.y, c[jj+2]+bb.z, c[jj+3]+bb.w);
        }
    }
}

// ---------------------------------------------------------------------------
extern "C" void kernel_launch(void* const* d_in, const int* in_sizes, int n_in,
                              void* d_out, int out_size)
{
    const float* x  = (const float*)d_in[0];
    const float* wq = (const float*)d_in[1];
    const float* wk = (const float*)d_in[2];
    const float* wv = (const float*)d_in[3];
    const float* wo = (const float*)d_in[4];
    const float* bo = (const float*)d_in[5];
    float* out = (float*)d_out;

    (void)in_sizes; (void)n_in; (void)out_size;

    const int attn_smem = (3*64*RP + 64*128) * 4;   // 134144 B
    cudaFuncSetAttribute(attn_kernel,
                         cudaFuncAttributeMaxDynamicSharedMemorySize, attn_smem);

    qkv_kernel<<<dim3(MROWS/128, DIM/128, 3), 256>>>(x, wq, wk, wv);
    attn_kernel<<<dim3(BHEADS, SEQ/128), 256, attn_smem>>>();
    proj_kernel<<<dim3(MROWS/128, DIM/128), 256>>>(wo, bo, out);
}

// round 5
// speedup vs baseline: 3.7743x; 3.7716x over previous
#include <cuda_runtime.h>
#include <cuda_bf16.h>
#include <math.h>
#include <stdint.h>

#define SEQ    4096
#define DIM    768
#define NH     12
#define HD     64
#define BATCH  2
#define MROWS  (BATCH*SEQ)
#define BHEADS (BATCH*NH)
#define QSCALE 0.18033688011112042f  /* 64^-0.5 * log2(e) */

// bf16 hi/lo split operands in [b,h,n,d]
__device__ __nv_bfloat16 g_qhi[(size_t)BHEADS*SEQ*HD];
__device__ __nv_bfloat16 g_qlo[(size_t)BHEADS*SEQ*HD];
__device__ __nv_bfloat16 g_khi[(size_t)BHEADS*SEQ*HD];
__device__ __nv_bfloat16 g_klo[(size_t)BHEADS*SEQ*HD];
__device__ __nv_bfloat16 g_vhi[(size_t)BHEADS*SEQ*HD];
__device__ __nv_bfloat16 g_vlo[(size_t)BHEADS*SEQ*HD];
__device__ __nv_bfloat16 g_atthi[(size_t)MROWS*DIM];
__device__ __nv_bfloat16 g_attlo[(size_t)MROWS*DIM];

// ---------------- helpers ----------------------------------------------------
__device__ __forceinline__ uint32_t smem_u32(const void* p){
    uint32_t a;
    asm("{ .reg .u64 t; cvta.to.shared.u64 t, %1; cvt.u32.u64 %0, t; }" : "=r"(a) : "l"(p));
    return a;
}
__device__ __forceinline__ void ldsm4(uint32_t* r, uint32_t a){
    asm volatile("ldmatrix.sync.aligned.m8n8.x4.shared.b16 {%0,%1,%2,%3}, [%4];"
        : "=r"(r[0]),"=r"(r[1]),"=r"(r[2]),"=r"(r[3]) : "r"(a));
}
__device__ __forceinline__ void ldsm4t(uint32_t* r, uint32_t a){
    asm volatile("ldmatrix.sync.aligned.m8n8.x4.trans.shared.b16 {%0,%1,%2,%3}, [%4];"
        : "=r"(r[0]),"=r"(r[1]),"=r"(r[2]),"=r"(r[3]) : "r"(a));
}
__device__ __forceinline__ void mma16816(float* c, const uint32_t* a, uint32_t b0, uint32_t b1){
    asm volatile("mma.sync.aligned.m16n8k16.row.col.f32.bf16.bf16.f32 "
        "{%0,%1,%2,%3}, {%4,%5,%6,%7}, {%8,%9}, {%0,%1,%2,%3};"
        : "+f"(c[0]),"+f"(c[1]),"+f"(c[2]),"+f"(c[3])
        : "r"(a[0]),"r"(a[1]),"r"(a[2]),"r"(a[3]), "r"(b0),"r"(b1));
}
__device__ __forceinline__ float ex2f(float x){
    float y; asm("ex2.approx.ftz.f32 %0, %1;" : "=f"(y) : "f"(x)); return y;
}
__device__ __forceinline__ uint32_t pk2(float lo, float hi){
    __nv_bfloat162 t = __floats2bfloat162_rn(lo, hi);   // x=lo(lower 16b), y=hi
    return *reinterpret_cast<uint32_t*>(&t);
}
__device__ __forceinline__ void split2(float f0, float f1, uint32_t& h, uint32_t& l){
    __nv_bfloat16 h0 = __float2bfloat16(f0), h1 = __float2bfloat16(f1);
    h = pk2(__bfloat162float(h0), __bfloat162float(h1));   // exact repack
    l = pk2(f0 - __bfloat162float(h0), f1 - __bfloat162float(h1));
}

// =============================================================================
// GEMM (qkv): C[128x128] = X @ W^T, k-chunk 32, bf16 3-split mma.
// smem rows padded to 40 bf16 (80B) -> conflict-free ldmatrix.
// =============================================================================
#define GP 40
#define GEMM_SMEM (4*128*GP*2)   /* 40960 B */

__global__ __launch_bounds__(256,1)
void qkv_mma(const float* __restrict__ x,  const float* __restrict__ wq,
             const float* __restrict__ wk, const float* __restrict__ wv)
{
    __shared__ __nv_bfloat16 smem[4*128*GP];
    __nv_bfloat16* Ahi = smem;
    __nv_bfloat16* Alo = smem + 128*GP;
    __nv_bfloat16* Bhi = smem + 2*128*GP;
    __nv_bfloat16* Blo = smem + 3*128*GP;
    const uint32_t sA_hi = smem_u32(Ahi), sA_lo = smem_u32(Alo);
    const uint32_t sB_hi = smem_u32(Bhi), sB_lo = smem_u32(Blo);

    const int z = blockIdx.z;
    const float* W = (z==0) ? wq : (z==1) ? wk : wv;
    __nv_bfloat16 *ohi, *olo;
    if (z==0)      { ohi = g_qhi; olo = g_qlo; }
    else if (z==1) { ohi = g_khi; olo = g_klo; }
    else           { ohi = g_vhi; olo = g_vlo; }

    const int tid = threadIdx.x, L = tid & 31, wid = tid >> 5;
    const int wm = (wid >> 2) * 64, wn = (wid & 3) * 32;
    const int m0 = blockIdx.x * 128, n0 = blockIdx.y * 128;

    const int lrow = tid >> 1, lks = (tid & 1) * 16;
    const float* ap = x + (size_t)(m0 + lrow)*DIM + lks;
    const float* bp = W + (size_t)(n0 + lrow)*DIM + lks;

    float acc[4][4][4];
#pragma unroll
    for (int i=0;i<4;i++)
#pragma unroll
        for (int j=0;j<4;j++)
#pragma unroll
            for (int e=0;e<4;e++) acc[i][j][e] = 0.f;

    for (int kc = 0; kc < DIM; kc += 32) {
        float4 af[4], bf[4];
#pragma unroll
        for (int i=0;i<4;i++){ af[i] = *(const float4*)(ap+kc+4*i); bf[i] = *(const float4*)(bp+kc+4*i); }
        __syncthreads();
        {
            __nv_bfloat16* dsth = Ahi + lrow*GP + lks;
            __nv_bfloat16* dstl = Alo + lrow*GP + lks;
#pragma unroll
            for (int i=0;i<4;i++){
                uint32_t h0,l0,h1,l1;
                split2(af[i].x, af[i].y, h0, l0);
                split2(af[i].z, af[i].w, h1, l1);
                *(uint2*)(dsth + 4*i) = make_uint2(h0,h1);
                *(uint2*)(dstl + 4*i) = make_uint2(l0,l1);
            }
            dsth = Bhi + lrow*GP + lks; dstl = Blo + lrow*GP + lks;
#pragma unroll
            for (int i=0;i<4;i++){
                uint32_t h0,l0,h1,l1;
                split2(bf[i].x, bf[i].y, h0, l0);
                split2(bf[i].z, bf[i].w, h1, l1);
                *(uint2*)(dsth + 4*i) = make_uint2(h0,h1);
                *(uint2*)(dstl + 4*i) = make_uint2(l0,l1);
            }
        }
        __syncthreads();
#pragma unroll
        for (int ks = 0; ks < 2; ks++) {
            uint32_t ahf[4][4], alf[4][4];
            uint32_t aoff = (uint32_t)(wm + (L & 15))*(GP*2) + ks*32 + (L >> 4)*16;
#pragma unroll
            for (int im=0; im<4; im++){
                ldsm4(ahf[im], sA_hi + aoff + im*16*(GP*2));
                ldsm4(alf[im], sA_lo + aoff + im*16*(GP*2));
            }
            uint32_t bhf[2][4], blf[2][4];
            uint32_t boff = (uint32_t)(wn + (L & 7) + ((L>>4)&1)*8)*(GP*2) + ks*32 + ((L>>3)&1)*16;
#pragma unroll
            for (int jn=0; jn<2; jn++){
                ldsm4(bhf[jn], sB_hi + boff + jn*16*(GP*2));
                ldsm4(blf[jn], sB_lo + boff + jn*16*(GP*2));
            }
#pragma unroll
            for (int im=0; im<4; im++)
#pragma unroll
                for (int n8=0; n8<4; n8++){
                    int jn = n8>>1, s = (n8&1)*2;
                    mma16816(acc[im][n8], ahf[im], bhf[jn][s], bhf[jn][s+1]);
                    mma16816(acc[im][n8], ahf[im], blf[jn][s], blf[jn][s+1]);
                    mma16816(acc[im][n8], alf[im], bhf[jn][s], bhf[jn][s+1]);
                }
        }
    }

    // epilogue: split to bf16 hi/lo, permuted store [b,h,n,d]; q scaled
    const float qs = (z==0) ? QSCALE : 1.f;
#pragma unroll
    for (int im=0; im<4; im++){
        int r0 = m0 + wm + im*16 + (L>>2);
#pragma unroll
        for (int n8=0; n8<4; n8++){
            int col = n0 + wn + n8*8 + 2*(L&3);
            int head = col >> 6, d = col & 63;
#pragma unroll
            for (int half=0; half<2; half++){
                int m = r0 + half*8;
                int b = m >> 12, n = m & (SEQ-1);
                float c0 = acc[im][n8][half*2]   * qs;
                float c1 = acc[im][n8][half*2+1] * qs;
                uint32_t h, l; split2(c0, c1, h, l);
                size_t a = ((size_t)(b*NH+head)*SEQ + n)*HD + d;
                *(uint32_t*)(ohi + a) = h;
                *(uint32_t*)(olo + a) = l;
            }
        }
    }
}

// =============================================================================
// Attention: CTA = 128 q rows, 32 KV tiles of 128.  Warp = 16 q x 128 kv.
// S = 3-split QK^T (mma), unnormalized exp2, P in regs, O += 3-split PV.
// smem: Khi/Klo/Vhi/Vlo tiles [128][72] bf16 = 73728 B (dynamic).
// =============================================================================
#define KVP 72
#define ATT_SMEM (4*128*KVP*2)

__global__ __launch_bounds__(256,1)
void attn_mma()
{
    extern __shared__ __nv_bfloat16 dsm[];
    __nv_bfloat16* Khi = dsm;
    __nv_bfloat16* Klo = dsm + 128*KVP;
    __nv_bfloat16* Vhi = dsm + 2*128*KVP;
    __nv_bfloat16* Vlo = dsm + 3*128*KVP;
    const uint32_t sK_hi = smem_u32(Khi), sK_lo = smem_u32(Klo);
    const uint32_t sV_hi = smem_u32(Vhi), sV_lo = smem_u32(Vlo);

    const int tid = threadIdx.x, L = tid & 31, w = tid >> 5;
    const int bh = blockIdx.x, q0 = blockIdx.y * 128;
    const size_t base = (size_t)bh * SEQ * HD;

    // ---- load Q tile into K smem region, pull A-frags into registers -------
    {
        int r = tid >> 1, half = (tid & 1) * 32;
        const uint4* qh = (const uint4*)(g_qhi + base + (size_t)(q0+r)*HD + half);
        const uint4* ql = (const uint4*)(g_qlo + base + (size_t)(q0+r)*HD + half);
        uint4* dh = (uint4*)(Khi + r*KVP + half);
        uint4* dl = (uint4*)(Klo + r*KVP + half);
#pragma unroll
        for (int i=0;i<4;i++){ dh[i] = qh[i]; dl[i] = ql[i]; }
    }
    __syncthreads();
    uint32_t qhf[4][4], qlf[4][4];
    {
        uint32_t aoff = (uint32_t)(w*16 + (L & 15))*(KVP*2) + (L >> 4)*16;
#pragma unroll
        for (int dg=0; dg<4; dg++){
            ldsm4(qhf[dg], sK_hi + aoff + dg*32);
            ldsm4(qlf[dg], sK_lo + aoff + dg*32);
        }
    }

    float o[8][4];
#pragma unroll
    for (int f=0;f<8;f++)
#pragma unroll
        for (int e=0;e<4;e++) o[f][e] = 0.f;
    float l0 = 0.f, l1 = 0.f;

    const int lrow = tid >> 1, lhalf = (tid & 1) * 32;

    for (int t = 0; t < SEQ/128; t++) {
        const int k0 = t * 128;
        __syncthreads();   // prev tile's consumers done
        {
            size_t g = base + (size_t)(k0+lrow)*HD + lhalf;
            const uint4* kh = (const uint4*)(g_khi + g);
            const uint4* kl = (const uint4*)(g_klo + g);
            const uint4* vh = (const uint4*)(g_vhi + g);
            const uint4* vl = (const uint4*)(g_vlo + g);
            uint4* d0 = (uint4*)(Khi + lrow*KVP + lhalf);
            uint4* d1 = (uint4*)(Klo + lrow*KVP + lhalf);
            uint4* d2 = (uint4*)(Vhi + lrow*KVP + lhalf);
            uint4* d3 = (uint4*)(Vlo + lrow*KVP + lhalf);
#pragma unroll
            for (int i=0;i<4;i++){ d0[i]=kh[i]; d1[i]=kl[i]; d2[i]=vh[i]; d3[i]=vl[i]; }
        }
        __syncthreads();

        // ---- S = Q K^T (16 x 128 per warp), 3-split ------------------------
        float s[16][4];
#pragma unroll
        for (int f=0;f<16;f++)
#pragma unroll
            for (int e=0;e<4;e++) s[f][e] = 0.f;
#pragma unroll
        for (int dg=0; dg<4; dg++){
#pragma unroll
            for (int j=0; j<8; j++){
                uint32_t boff = (uint32_t)(j*16 + (L & 7) + ((L>>4)&1)*8)*(KVP*2)
                              + dg*32 + ((L>>3)&1)*16;
                uint32_t bh4[4], bl4[4];
                ldsm4(bh4, sK_hi + boff);
                ldsm4(bl4, sK_lo + boff);
                mma16816(s[2*j],   qhf[dg], bh4[0], bh4[1]);
                mma16816(s[2*j],   qhf[dg], bl4[0], bl4[1]);
                mma16816(s[2*j],   qlf[dg], bh4[0], bh4[1]);
                mma16816(s[2*j+1], qhf[dg], bh4[2], bh4[3]);
                mma16816(s[2*j+1], qhf[dg], bl4[2], bl4[3]);
                mma16816(s[2*j+1], qlf[dg], bh4[2], bh4[3]);
            }
        }

        // ---- unnormalized exp2 + row-sum accumulation ----------------------
        float sum0 = 0.f, sum1 = 0.f;
#pragma unroll
        for (int f=0;f<16;f++){
            s[f][0] = ex2f(s[f][0]); s[f][1] = ex2f(s[f][1]);
            s[f][2] = ex2f(s[f][2]); s[f][3] = ex2f(s[f][3]);
            sum0 += s[f][0] + s[f][1];
            sum1 += s[f][2] + s[f][3];
        }
        sum0 += __shfl_xor_sync(0xffffffffu, sum0, 1);
        sum0 += __shfl_xor_sync(0xffffffffu, sum0, 2);
        sum1 += __shfl_xor_sync(0xffffffffu, sum1, 1);
        sum1 += __shfl_xor_sync(0xffffffffu, sum1, 2);
        l0 += sum0; l1 += sum1;

        // ---- O += P V (P from S regs: C-frag == A-frag layout) -------------
#pragma unroll
        for (int kg=0; kg<8; kg++){
            uint32_t phi[4], plo[4];
            split2(s[2*kg][0],   s[2*kg][1],   phi[0], plo[0]);
            split2(s[2*kg][2],   s[2*kg][3],   phi[1], plo[1]);
            split2(s[2*kg+1][0], s[2*kg+1][1], phi[2], plo[2]);
            split2(s[2*kg+1][2], s[2*kg+1][3], phi[3], plo[3]);
#pragma unroll
            for (int j=0; j<4; j++){
                uint32_t voff = (uint32_t)(kg*16 + (L & 7) + ((L>>3)&1)*8)*(KVP*2)
                              + j*32 + ((L>>4)&1)*16;
                uint32_t vh4[4], vl4[4];
                ldsm4t(vh4, sV_hi + voff);
                ldsm4t(vl4, sV_lo + voff);
                mma16816(o[2*j],   phi, vh4[0], vh4[1]);
                mma16816(o[2*j],   phi, vl4[0], vl4[1]);
                mma16816(o[2*j],   plo, vh4[0], vh4[1]);
                mma16816(o[2*j+1], phi, vh4[2], vh4[3]);
                mma16816(o[2*j+1], phi, vl4[2], vl4[3]);
                mma16816(o[2*j+1], plo, vh4[2], vh4[3]);
            }
        }
    }

    // ---- epilogue: normalize, split, store [b, n, dim] -------------------
    const int b = bh / NH, head = bh % NH;
    const float inv0 = 1.f / l0, inv1 = 1.f / l1;
    const int r0 = q0 + w*16 + (L>>2);
#pragma unroll
    for (int f=0;f<8;f++){
        int col = f*8 + 2*(L&3);
        size_t a0 = ((size_t)b*SEQ + r0)  *DIM + head*HD + col;
        size_t a1 = ((size_t)b*SEQ + r0+8)*DIM + head*HD + col;
        uint32_t h, l;
        split2(o[f][0]*inv0, o[f][1]*inv0, h, l);
        *(uint32_t*)(g_atthi + a0) = h; *(uint32_t*)(g_attlo + a0) = l;
        split2(o[f][2]*inv1, o[f][3]*inv1, h, l);
        *(uint32_t*)(g_atthi + a1) = h; *(uint32_t*)(g_attlo + a1) = l;
    }
}

// =============================================================================
// Output projection: out = att @ wo^T + bo (A already split bf16; fp32 out)
// =============================================================================
__global__ __launch_bounds__(256,1)
void proj_mma(const float* __restrict__ wo, const float* __restrict__ bo,
              float* __restrict__ out)
{
    __shared__ __nv_bfloat16 smem[4*128*GP];
    __nv_bfloat16* Ahi = smem;
    __nv_bfloat16* Alo = smem + 128*GP;
    __nv_bfloat16* Bhi = smem + 2*128*GP;
    __nv_bfloat16* Blo = smem + 3*128*GP;
    const uint32_t sA_hi = smem_u32(Ahi), sA_lo = smem_u32(Alo);
    const uint32_t sB_hi = smem_u32(Bhi), sB_lo = smem_u32(Blo);

    const int tid = threadIdx.x, L = tid & 31, wid = tid >> 5;
    const int wm = (wid >> 2) * 64, wn = (wid & 3) * 32;
    const int m0 = blockIdx.x * 128, n0 = blockIdx.y * 128;

    const int lrow = tid >> 1, lks = (tid & 1) * 16;
    const __nv_bfloat16* ahp = g_atthi + (size_t)(m0+lrow)*DIM + lks;
    const __nv_bfloat16* alp = g_attlo + (size_t)(m0+lrow)*DIM + lks;
    const float* bp = wo + (size_t)(n0+lrow)*DIM + lks;

    float acc[4][4][4];
#pragma unroll
    for (int i=0;i<4;i++)
#pragma unroll
        for (int j=0;j<4;j++)
#pragma unroll
            for (int e=0;e<4;e++) acc[i][j][e] = 0.f;

    for (int kc = 0; kc < DIM; kc += 32) {
        uint4 a0 = *(const uint4*)(ahp+kc), a1 = *(const uint4*)(ahp+kc+8);
        uint4 c0 = *(const uint4*)(alp+kc), c1 = *(const uint4*)(alp+kc+8);
        float4 bf[4];
#pragma unroll
        for (int i=0;i<4;i++) bf[i] = *(const float4*)(bp+kc+4*i);
        __syncthreads();
        *(uint4*)(Ahi + lrow*GP + lks)     = a0;
        *(uint4*)(Ahi + lrow*GP + lks + 8) = a1;
        *(uint4*)(Alo + lrow*GP + lks)     = c0;
        *(uint4*)(Alo + lrow*GP + lks + 8) = c1;
        {
            __nv_bfloat16* dsth = Bhi + lrow*GP + lks;
            __nv_bfloat16* dstl = Blo + lrow*GP + lks;
#pragma unroll
            for (int i=0;i<4;i++){
                uint32_t h0,l0,h1,l1;
                split2(bf[i].x, bf[i].y, h0, l0);
                split2(bf[i].z, bf[i].w, h1, l1);
                *(uint2*)(dsth + 4*i) = make_uint2(h0,h1);
                *(uint2*)(dstl + 4*i) = make_uint2(l0,l1);
            }
        }
        __syncthreads();
#pragma unroll
        for (int ks = 0; ks < 2; ks++) {
            uint32_t ahf[4][4], alf[4][4];
            uint32_t aoff = (uint32_t)(wm + (L & 15))*(GP*2) + ks*32 + (L >> 4)*16;
#pragma unroll
            for (int im=0; im<4; im++){
                ldsm4(ahf[im], sA_hi + aoff + im*16*(GP*2));
                ldsm4(alf[im], sA_lo + aoff + im*16*(GP*2));
            }
            uint32_t bhf[2][4], blf[2][4];
            uint32_t boff = (uint32_t)(wn + (L & 7) + ((L>>4)&1)*8)*(GP*2) + ks*32 + ((L>>3)&1)*16;
#pragma unroll
            for (int jn=0; jn<2; jn++){
                ldsm4(bhf[jn], sB_hi + boff + jn*16*(GP*2));
                ldsm4(blf[jn], sB_lo + boff + jn*16*(GP*2));
            }
#pragma unroll
            for (int im=0; im<4; im++)
#pragma unroll
                for (int n8=0; n8<4; n8++){
                    int jn = n8>>1, ss = (n8&1)*2;
                    mma16816(acc[im][n8], ahf[im], bhf[jn][ss], bhf[jn][ss+1]);
                    mma16816(acc[im][n8], ahf[im], blf[jn][ss], blf[jn][ss+1]);
                    mma16816(acc[im][n8], alf[im], bhf[jn][ss], bhf[jn][ss+1]);
                }
        }
    }

#pragma unroll
    for (int im=0; im<4; im++){
        int r0 = m0 + wm + im*16 + (L>>2);
#pragma unroll
        for (int n8=0; n8<4; n8++){
            int col = n0 + wn + n8*8 + 2*(L&3);
            float b0 = bo[col], b1 = bo[col+1];
            *(float2*)(out + (size_t)r0*DIM + col) =
                make_float2(acc[im][n8][0]+b0, acc[im][n8][1]+b1);
            *(float2*)(out + (size_t)(r0+8)*DIM + col) =
                make_float2(acc[im][n8][2]+b0, acc[im][n8][3]+b1);
        }
    }
}

// -----------------------------------------------------------------------------
extern "C" void kernel_launch(void* const* d_in, const int* in_sizes, int n_in,
                              void* d_out, int out_size)
{
    const float* x  = (const float*)d_in[0];
    const float* wq = (const float*)d_in[1];
    const float* wk = (const float*)d_in[2];
    const float* wv = (const float*)d_in[3];
    const float* wo = (const float*)d_in[4];
    const float* bo = (const float*)d_in[5];
    float* out = (float*)d_out;
    (void)in_sizes; (void)n_in; (void)out_size;

    cudaFuncSetAttribute(attn_mma, cudaFuncAttributeMaxDynamicSharedMemorySize, ATT_SMEM);

    qkv_mma <<<dim3(MROWS/128, DIM/128, 3), 256>>>(x, wq, wk, wv);
    attn_mma<<<dim3(BHEADS, SEQ/128),       256, ATT_SMEM>>>();
    proj_mma<<<dim3(MROWS/128, DIM/128),    256>>>(wo, bo, out);
}

// round 6
// speedup vs baseline: 3.8261x; 1.0137x over previous
#include <cuda_runtime.h>
#include <cuda_bf16.h>
#include <math.h>
#include <stdint.h>

#define SEQ    4096
#define DIM    768
#define NH     12
#define HD     64
#define BATCH  2
#define MROWS  (BATCH*SEQ)
#define BHEADS (BATCH*NH)
#define QSCALE 0.18033688011112042f  /* 64^-0.5 * log2(e) */

// pre-split bf16 hi/lo inputs
__device__ __nv_bfloat16 g_xhi[(size_t)MROWS*DIM];
__device__ __nv_bfloat16 g_xlo[(size_t)MROWS*DIM];
__device__ __nv_bfloat16 g_wqhi[(size_t)DIM*DIM];
__device__ __nv_bfloat16 g_wqlo[(size_t)DIM*DIM];
__device__ __nv_bfloat16 g_wkhi[(size_t)DIM*DIM];
__device__ __nv_bfloat16 g_wklo[(size_t)DIM*DIM];
__device__ __nv_bfloat16 g_wvhi[(size_t)DIM*DIM];
__device__ __nv_bfloat16 g_wvlo[(size_t)DIM*DIM];
__device__ __nv_bfloat16 g_wohi[(size_t)DIM*DIM];
__device__ __nv_bfloat16 g_wolo[(size_t)DIM*DIM];
// bf16 hi/lo split intermediates, [b,h,n,d]
__device__ __nv_bfloat16 g_qhi[(size_t)BHEADS*SEQ*HD];
__device__ __nv_bfloat16 g_qlo[(size_t)BHEADS*SEQ*HD];
__device__ __nv_bfloat16 g_khi[(size_t)BHEADS*SEQ*HD];
__device__ __nv_bfloat16 g_klo[(size_t)BHEADS*SEQ*HD];
__device__ __nv_bfloat16 g_vhi[(size_t)BHEADS*SEQ*HD];
__device__ __nv_bfloat16 g_vlo[(size_t)BHEADS*SEQ*HD];
__device__ __nv_bfloat16 g_atthi[(size_t)MROWS*DIM];
__device__ __nv_bfloat16 g_attlo[(size_t)MROWS*DIM];

// ---------------- helpers ----------------------------------------------------
__device__ __forceinline__ uint32_t smem_u32(const void* p){
    uint32_t a;
    asm("{ .reg .u64 t; cvta.to.shared.u64 t, %1; cvt.u32.u64 %0, t; }" : "=r"(a) : "l"(p));
    return a;
}
__device__ __forceinline__ void ldsm4(uint32_t* r, uint32_t a){
    asm volatile("ldmatrix.sync.aligned.m8n8.x4.shared.b16 {%0,%1,%2,%3}, [%4];"
        : "=r"(r[0]),"=r"(r[1]),"=r"(r[2]),"=r"(r[3]) : "r"(a));
}
__device__ __forceinline__ void ldsm4t(uint32_t* r, uint32_t a){
    asm volatile("ldmatrix.sync.aligned.m8n8.x4.trans.shared.b16 {%0,%1,%2,%3}, [%4];"
        : "=r"(r[0]),"=r"(r[1]),"=r"(r[2]),"=r"(r[3]) : "r"(a));
}
__device__ __forceinline__ void mma16816(float* c, const uint32_t* a, uint32_t b0, uint32_t b1){
    asm volatile("mma.sync.aligned.m16n8k16.row.col.f32.bf16.bf16.f32 "
        "{%0,%1,%2,%3}, {%4,%5,%6,%7}, {%8,%9}, {%0,%1,%2,%3};"
        : "+f"(c[0]),"+f"(c[1]),"+f"(c[2]),"+f"(c[3])
        : "r"(a[0]),"r"(a[1]),"r"(a[2]),"r"(a[3]), "r"(b0),"r"(b1));
}
__device__ __forceinline__ float ex2f(float x){
    float y; asm("ex2.approx.ftz.f32 %0, %1;" : "=f"(y) : "f"(x)); return y;
}
__device__ __forceinline__ uint32_t pk2(float lo, float hi){
    __nv_bfloat162 t = __floats2bfloat162_rn(lo, hi);
    return *reinterpret_cast<uint32_t*>(&t);
}
__device__ __forceinline__ void split2(float f0, float f1, uint32_t& h, uint32_t& l){
    __nv_bfloat16 h0 = __float2bfloat16(f0), h1 = __float2bfloat16(f1);
    h = pk2(__bfloat162float(h0), __bfloat162float(h1));
    l = pk2(f0 - __bfloat162float(h0), f1 - __bfloat162float(h1));
}
#define CPA(d,s)   asm volatile("cp.async.cg.shared.global [%0], [%1], 16;" :: "r"((uint32_t)(d)), "l"(s) : "memory")
#define CPCOMMIT() asm volatile("cp.async.commit_group;" ::: "memory")
#define CPWAIT1()  asm volatile("cp.async.wait_group 1;" ::: "memory")
#define CPWAIT0()  asm volatile("cp.async.wait_group 0;" ::: "memory")

// =============================================================================
// input split: fp32 -> bf16 hi/lo
// =============================================================================
__global__ void split_f32(const float4* __restrict__ src,
                          uint2* __restrict__ hi, uint2* __restrict__ lo, int n4)
{
    int i = blockIdx.x*blockDim.x + threadIdx.x;
    if (i < n4){
        float4 f = src[i];
        uint32_t h0,l0,h1,l1;
        split2(f.x, f.y, h0, l0);
        split2(f.z, f.w, h1, l1);
        hi[i] = make_uint2(h0,h1);
        lo[i] = make_uint2(l0,l1);
    }
}

// =============================================================================
// GEMM tiles: 128x128 CTA, 8 warps (2x4), k-chunk 64, double-buffered cp.async.
// smem per stage: Ahi|Alo|Bhi|Blo, each [128][72] bf16 (144B rows, ldsm-clean).
// =============================================================================
#define GPE  72
#define ARR  (128*GPE*2)        /* 18432 B per array */
#define STG  (4*ARR)            /* 73728 B per stage */
#define GEMM_SMEM (2*STG)       /* 147456 B */

struct Frag { float v[4]; };

// prefetch one k-chunk (64 cols) of A/B hi/lo into stage s
__device__ __forceinline__ void gemm_pf(
    uint32_t sb, int s, int c, int row, int half,
    const __nv_bfloat16* Ah, const __nv_bfloat16* Al,
    const __nv_bfloat16* Bh, const __nv_bfloat16* Bl)
{
    uint32_t base = sb + s*STG + (uint32_t)(row*GPE + half)*2;
    const size_t g = (size_t)c*64 + half;
#pragma unroll
    for (int u = 0; u < 4; u++){
        CPA(base + 0*ARR + u*16, Ah + g + u*8);
        CPA(base + 1*ARR + u*16, Al + g + u*8);
        CPA(base + 2*ARR + u*16, Bh + g + u*8);
        CPA(base + 3*ARR + u*16, Bl + g + u*8);
    }
}

__device__ __forceinline__ void gemm_compute(
    uint32_t sb, int s, int wm, int wn, int L, float acc[4][4][4])
{
    const uint32_t bA_hi = sb + s*STG, bA_lo = bA_hi + ARR;
    const uint32_t bB_hi = bA_hi + 2*ARR, bB_lo = bA_hi + 3*ARR;
#pragma unroll
    for (int ks = 0; ks < 4; ks++){
        uint32_t ahf[4][4], alf[4][4];
        uint32_t aoff = (uint32_t)(wm + (L & 15))*(GPE*2) + ks*32 + (L >> 4)*16;
#pragma unroll
        for (int im=0; im<4; im++){
            ldsm4(ahf[im], bA_hi + aoff + im*16*(GPE*2));
            ldsm4(alf[im], bA_lo + aoff + im*16*(GPE*2));
        }
        uint32_t bhf[2][4], blf[2][4];
        uint32_t boff = (uint32_t)(wn + (L & 7) + ((L>>4)&1)*8)*(GPE*2) + ks*32 + ((L>>3)&1)*16;
#pragma unroll
        for (int jn=0; jn<2; jn++){
            ldsm4(bhf[jn], bB_hi + boff + jn*16*(GPE*2));
            ldsm4(blf[jn], bB_lo + boff + jn*16*(GPE*2));
        }
#pragma unroll
        for (int im=0; im<4; im++)
#pragma unroll
            for (int n8=0; n8<4; n8++){
                int jn = n8>>1, ss = (n8&1)*2;
                mma16816(acc[im][n8], ahf[im], bhf[jn][ss], bhf[jn][ss+1]);
                mma16816(acc[im][n8], ahf[im], blf[jn][ss], blf[jn][ss+1]);
                mma16816(acc[im][n8], alf[im], bhf[jn][ss], bhf[jn][ss+1]);
            }
    }
}

__global__ __launch_bounds__(256,1)
void qkv_mma()
{
    extern __shared__ __nv_bfloat16 dsm[];
    const uint32_t sb = smem_u32(dsm);
    const int z = blockIdx.z;
    const __nv_bfloat16 *Bh, *Bl;
    __nv_bfloat16 *ohi, *olo;
    if (z==0)      { Bh = g_wqhi; Bl = g_wqlo; ohi = g_qhi; olo = g_qlo; }
    else if (z==1) { Bh = g_wkhi; Bl = g_wklo; ohi = g_khi; olo = g_klo; }
    else           { Bh = g_wvhi; Bl = g_wvlo; ohi = g_vhi; olo = g_vlo; }

    const int tid = threadIdx.x, L = tid & 31, wid = tid >> 5;
    const int wm = (wid >> 2) * 64, wn = (wid & 3) * 32;
    const int m0 = blockIdx.x * 128, n0 = blockIdx.y * 128;
    const int row = tid >> 1, half = (tid & 1) * 32;

    const __nv_bfloat16* Ah = g_xhi + (size_t)(m0+row)*DIM;
    const __nv_bfloat16* Al = g_xlo + (size_t)(m0+row)*DIM;
    const __nv_bfloat16* Bhp = Bh + (size_t)(n0+row)*DIM;
    const __nv_bfloat16* Blp = Bl + (size_t)(n0+row)*DIM;

    float acc[4][4][4];
#pragma unroll
    for (int i=0;i<4;i++)
#pragma unroll
        for (int j=0;j<4;j++)
#pragma unroll
            for (int e=0;e<4;e++) acc[i][j][e] = 0.f;

    gemm_pf(sb, 0, 0, row, half, Ah, Al, Bhp, Blp);
    CPCOMMIT();
    for (int c = 0; c < 12; c++){
        if (c < 11){ gemm_pf(sb, (c+1)&1, c+1, row, half, Ah, Al, Bhp, Blp); CPCOMMIT(); CPWAIT1(); }
        else CPWAIT0();
        __syncthreads();
        gemm_compute(sb, c&1, wm, wn, L, acc);
        __syncthreads();
    }

    // epilogue: split to bf16 hi/lo, permuted store [b,h,n,d]; q scaled
    const float qs = (z==0) ? QSCALE : 1.f;
#pragma unroll
    for (int im=0; im<4; im++){
        int r0 = m0 + wm + im*16 + (L>>2);
#pragma unroll
        for (int n8=0; n8<4; n8++){
            int col = n0 + wn + n8*8 + 2*(L&3);
            int head = col >> 6, d = col & 63;
#pragma unroll
            for (int hf2=0; hf2<2; hf2++){
                int m = r0 + hf2*8;
                int b = m >> 12, n = m & (SEQ-1);
                uint32_t h, l;
                split2(acc[im][n8][hf2*2]*qs, acc[im][n8][hf2*2+1]*qs, h, l);
                size_t a = ((size_t)(b*NH+head)*SEQ + n)*HD + d;
                *(uint32_t*)(ohi + a) = h;
                *(uint32_t*)(olo + a) = l;
            }
        }
    }
}

__global__ __launch_bounds__(256,1)
void proj_mma(const float* __restrict__ bo, float* __restrict__ out)
{
    extern __shared__ __nv_bfloat16 dsm[];
    const uint32_t sb = smem_u32(dsm);
    const int tid = threadIdx.x, L = tid & 31, wid = tid >> 5;
    const int wm = (wid >> 2) * 64, wn = (wid & 3) * 32;
    const int m0 = blockIdx.x * 128, n0 = blockIdx.y * 128;
    const int row = tid >> 1, half = (tid & 1) * 32;

    const __nv_bfloat16* Ah = g_atthi + (size_t)(m0+row)*DIM;
    const __nv_bfloat16* Al = g_attlo + (size_t)(m0+row)*DIM;
    const __nv_bfloat16* Bh = g_wohi + (size_t)(n0+row)*DIM;
    const __nv_bfloat16* Bl = g_wolo + (size_t)(n0+row)*DIM;

    float acc[4][4][4];
#pragma unroll
    for (int i=0;i<4;i++)
#pragma unroll
        for (int j=0;j<4;j++)
#pragma unroll
            for (int e=0;e<4;e++) acc[i][j][e] = 0.f;

    gemm_pf(sb, 0, 0, row, half, Ah, Al, Bh, Bl);
    CPCOMMIT();
    for (int c = 0; c < 12; c++){
        if (c < 11){ gemm_pf(sb, (c+1)&1, c+1, row, half, Ah, Al, Bh, Bl); CPCOMMIT(); CPWAIT1(); }
        else CPWAIT0();
        __syncthreads();
        gemm_compute(sb, c&1, wm, wn, L, acc);
        __syncthreads();
    }

#pragma unroll
    for (int im=0; im<4; im++){
        int r0 = m0 + wm + im*16 + (L>>2);
#pragma unroll
        for (int n8=0; n8<4; n8++){
            int col = n0 + wn + n8*8 + 2*(L&3);
            float b0 = bo[col], b1 = bo[col+1];
            *(float2*)(out + (size_t)r0*DIM + col) =
                make_float2(acc[im][n8][0]+b0, acc[im][n8][1]+b1);
            *(float2*)(out + (size_t)(r0+8)*DIM + col) =
                make_float2(acc[im][n8][2]+b0, acc[im][n8][3]+b1);
        }
    }
}

// =============================================================================
// Attention: CTA = 128 q x 32 KV tiles of 128; double-buffered cp.async KV.
// smem per stage: Khi|Klo|Vhi|Vlo each [128][72] bf16. 2 stages = 147456 B.
// =============================================================================
#define KVP 72
#define AARR (128*KVP*2)
#define ASTG (4*AARR)
#define ATT_SMEM (2*ASTG)

__device__ __forceinline__ void attn_pf(uint32_t sb, int s, int k0, int row, int half,
                                        size_t base)
{
    uint32_t d = sb + s*ASTG + (uint32_t)(row*KVP + half)*2;
    size_t g = base + (size_t)(k0+row)*HD + half;
#pragma unroll
    for (int u = 0; u < 4; u++){
        CPA(d + 0*AARR + u*16, g_khi + g + u*8);
        CPA(d + 1*AARR + u*16, g_klo + g + u*8);
        CPA(d + 2*AARR + u*16, g_vhi + g + u*8);
        CPA(d + 3*AARR + u*16, g_vlo + g + u*8);
    }
}

__global__ __launch_bounds__(256,1)
void attn_mma()
{
    extern __shared__ __nv_bfloat16 dsm[];
    const uint32_t sb = smem_u32(dsm);
    const int tid = threadIdx.x, L = tid & 31, w = tid >> 5;
    const int bh = blockIdx.x, q0 = blockIdx.y * 128;
    const size_t base = (size_t)bh * SEQ * HD;
    const int row = tid >> 1, half = (tid & 1) * 32;

    // ---- Q tile through stage-0 smem -> A-frags in registers ---------------
    {
        const uint4* qh = (const uint4*)(g_qhi + base + (size_t)(q0+row)*HD + half);
        const uint4* ql = (const uint4*)(g_qlo + base + (size_t)(q0+row)*HD + half);
        uint4* dh = (uint4*)(dsm + row*KVP + half);
        uint4* dl = (uint4*)(dsm + 128*KVP + row*KVP + half);
#pragma unroll
        for (int i=0;i<4;i++){ dh[i] = qh[i]; dl[i] = ql[i]; }
    }
    __syncthreads();
    uint32_t qhf[4][4], qlf[4][4];
    {
        uint32_t aoff = (uint32_t)(w*16 + (L & 15))*(KVP*2) + (L >> 4)*16;
#pragma unroll
        for (int dg=0; dg<4; dg++){
            ldsm4(qhf[dg], sb + aoff + dg*32);
            ldsm4(qlf[dg], sb + AARR + aoff + dg*32);
        }
    }
    __syncthreads();

    float o[8][4];
#pragma unroll
    for (int f=0;f<8;f++)
#pragma unroll
        for (int e=0;e<4;e++) o[f][e] = 0.f;
    float l0 = 0.f, l1 = 0.f;

    attn_pf(sb, 0, 0, row, half, base);
    CPCOMMIT();

    for (int t = 0; t < SEQ/128; t++) {
        if (t < 31){ attn_pf(sb, (t+1)&1, (t+1)*128, row, half, base); CPCOMMIT(); CPWAIT1(); }
        else CPWAIT0();
        __syncthreads();
        const uint32_t sK_hi = sb + (t&1)*ASTG;
        const uint32_t sK_lo = sK_hi + AARR;
        const uint32_t sV_hi = sK_hi + 2*AARR;
        const uint32_t sV_lo = sK_hi + 3*AARR;

        // ---- S = Q K^T (16 x 128 per warp), 3-split ------------------------
        float s[16][4];
#pragma unroll
        for (int f=0;f<16;f++)
#pragma unroll
            for (int e=0;e<4;e++) s[f][e] = 0.f;
#pragma unroll
        for (int dg=0; dg<4; dg++){
#pragma unroll
            for (int j=0; j<8; j++){
                uint32_t boff = (uint32_t)(j*16 + (L & 7) + ((L>>4)&1)*8)*(KVP*2)
                              + dg*32 + ((L>>3)&1)*16;
                uint32_t bh4[4], bl4[4];
                ldsm4(bh4, sK_hi + boff);
                ldsm4(bl4, sK_lo + boff);
                mma16816(s[2*j],   qhf[dg], bh4[0], bh4[1]);
                mma16816(s[2*j],   qhf[dg], bl4[0], bl4[1]);
                mma16816(s[2*j],   qlf[dg], bh4[0], bh4[1]);
                mma16816(s[2*j+1], qhf[dg], bh4[2], bh4[3]);
                mma16816(s[2*j+1], qhf[dg], bl4[2], bl4[3]);
                mma16816(s[2*j+1], qlf[dg], bh4[2], bh4[3]);
            }
        }

        // ---- unnormalized exp2 + row-sum ------------------------------------
        float sum0 = 0.f, sum1 = 0.f;
#pragma unroll
        for (int f=0;f<16;f++){
            s[f][0] = ex2f(s[f][0]); s[f][1] = ex2f(s[f][1]);
            s[f][2] = ex2f(s[f][2]); s[f][3] = ex2f(s[f][3]);
            sum0 += s[f][0] + s[f][1];
            sum1 += s[f][2] + s[f][3];
        }
        sum0 += __shfl_xor_sync(0xffffffffu, sum0, 1);
        sum0 += __shfl_xor_sync(0xffffffffu, sum0, 2);
        sum1 += __shfl_xor_sync(0xffffffffu, sum1, 1);
        sum1 += __shfl_xor_sync(0xffffffffu, sum1, 2);
        l0 += sum0; l1 += sum1;

        // ---- O += P V --------------------------------------------------------
#pragma unroll
        for (int kg=0; kg<8; kg++){
            uint32_t phi[4], plo[4];
            split2(s[2*kg][0],   s[2*kg][1],   phi[0], plo[0]);
            split2(s[2*kg][2],   s[2*kg][3],   phi[1], plo[1]);
            split2(s[2*kg+1][0], s[2*kg+1][1], phi[2], plo[2]);
            split2(s[2*kg+1][2], s[2*kg+1][3], phi[3], plo[3]);
#pragma unroll
            for (int j=0; j<4; j++){
                uint32_t voff = (uint32_t)(kg*16 + (L & 7) + ((L>>3)&1)*8)*(KVP*2)
                              + j*32 + ((L>>4)&1)*16;
                uint32_t vh4[4], vl4[4];
                ldsm4t(vh4, sV_hi + voff);
                ldsm4t(vl4, sV_lo + voff);
                mma16816(o[2*j],   phi, vh4[0], vh4[1]);
                mma16816(o[2*j],   phi, vl4[0], vl4[1]);
                mma16816(o[2*j],   plo, vh4[0], vh4[1]);
                mma16816(o[2*j+1], phi, vh4[2], vh4[3]);
                mma16816(o[2*j+1], phi, vl4[2], vl4[3]);
                mma16816(o[2*j+1], plo, vh4[2], vh4[3]);
            }
        }
        __syncthreads();
    }

    // ---- epilogue: normalize, split, store [b, n, dim] ----------------------
    const int b = bh / NH, head = bh % NH;
    const float inv0 = 1.f / l0, inv1 = 1.f / l1;
    const int r0 = q0 + w*16 + (L>>2);
#pragma unroll
    for (int f=0;f<8;f++){
        int col = f*8 + 2*(L&3);
        size_t a0 = ((size_t)b*SEQ + r0)  *DIM + head*HD + col;
        size_t a1 = ((size_t)b*SEQ + r0+8)*DIM + head*HD + col;
        uint32_t h, l;
        split2(o[f][0]*inv0, o[f][1]*inv0, h, l);
        *(uint32_t*)(g_atthi + a0) = h; *(uint32_t*)(g_attlo + a0) = l;
        split2(o[f][2]*inv1, o[f][3]*inv1, h, l);
        *(uint32_t*)(g_atthi + a1) = h; *(uint32_t*)(g_attlo + a1) = l;
    }
}

// -----------------------------------------------------------------------------
extern "C" void kernel_launch(void* const* d_in, const int* in_sizes, int n_in,
                              void* d_out, int out_size)
{
    const float* x  = (const float*)d_in[0];
    const float* wq = (const float*)d_in[1];
    const float* wk = (const float*)d_in[2];
    const float* wv = (const float*)d_in[3];
    const float* wo = (const float*)d_in[4];
    const float* bo = (const float*)d_in[5];
    float* out = (float*)d_out;
    (void)in_sizes; (void)n_in; (void)out_size;

    static __nv_bfloat16 *xh, *xl, *qh, *ql, *kh, *kl, *vh, *vl, *oh, *ol;
    cudaGetSymbolAddress((void**)&xh, g_xhi);  cudaGetSymbolAddress((void**)&xl, g_xlo);
    cudaGetSymbolAddress((void**)&qh, g_wqhi); cudaGetSymbolAddress((void**)&ql, g_wqlo);
    cudaGetSymbolAddress((void**)&kh, g_wkhi); cudaGetSymbolAddress((void**)&kl, g_wklo);
    cudaGetSymbolAddress((void**)&vh, g_wvhi); cudaGetSymbolAddress((void**)&vl, g_wvlo);
    cudaGetSymbolAddress((void**)&oh, g_wohi); cudaGetSymbolAddress((void**)&ol, g_wolo);

    cudaFuncSetAttribute(qkv_mma,  cudaFuncAttributeMaxDynamicSharedMemorySize, GEMM_SMEM);
    cudaFuncSetAttribute(attn_mma, cudaFuncAttributeMaxDynamicSharedMemorySize, ATT_SMEM);
    cudaFuncSetAttribute(proj_mma, cudaFuncAttributeMaxDynamicSharedMemorySize, GEMM_SMEM);

    const int nx4 = MROWS*DIM/4, nw4 = DIM*DIM/4;
    split_f32<<<(nx4+255)/256, 256>>>((const float4*)x,  (uint2*)xh, (uint2*)xl, nx4);
    split_f32<<<(nw4+255)/256, 256>>>((const float4*)wq, (uint2*)qh, (uint2*)ql, nw4);
    split_f32<<<(nw4+255)/256, 256>>>((const float4*)wk, (uint2*)kh, (uint2*)kl, nw4);
    split_f32<<<(nw4+255)/256, 256>>>((const float4*)wv, (uint2*)vh, (uint2*)vl, nw4);
    split_f32<<<(nw4+255)/256, 256>>>((const float4*)wo, (uint2*)oh, (uint2*)ol, nw4);

    qkv_mma <<<dim3(MROWS/128, DIM/128, 3), 256, GEMM_SMEM>>>();
    attn_mma<<<dim3(BHEADS, SEQ/128),       256, ATT_SMEM>>>();
    proj_mma<<<dim3(MROWS/128, DIM/128),    256, GEMM_SMEM>>>(bo, out);
}

// round 7
// speedup vs baseline: 6.8569x; 1.7922x over previous
#include <cuda_runtime.h>
#include <cuda_fp16.h>
#include <math.h>
#include <stdint.h>

#define SEQ    4096
#define DIM    768
#define NH     12
#define HD     64
#define BATCH  2
#define MROWS  (BATCH*SEQ)
#define BHEADS (BATCH*NH)
#define QSCALE 0.18033688011112042f  /* 64^-0.5 * log2(e) */

// fp16 operands: A-side split (hi+lo), B-side hi only
__device__ __half g_xhi[(size_t)MROWS*DIM];
__device__ __half g_xlo[(size_t)MROWS*DIM];
__device__ __half g_wqhi[(size_t)DIM*DIM];
__device__ __half g_wkhi[(size_t)DIM*DIM];
__device__ __half g_wvhi[(size_t)DIM*DIM];
__device__ __half g_wohi[(size_t)DIM*DIM];
__device__ __half g_qhi[(size_t)BHEADS*SEQ*HD];
__device__ __half g_qlo[(size_t)BHEADS*SEQ*HD];
__device__ __half g_khi[(size_t)BHEADS*SEQ*HD];
__device__ __half g_vhi[(size_t)BHEADS*SEQ*HD];
__device__ __half g_atthi[(size_t)MROWS*DIM];
__device__ __half g_attlo[(size_t)MROWS*DIM];

// ---------------- helpers ----------------------------------------------------
__device__ __forceinline__ uint32_t smem_u32(const void* p){
    uint32_t a;
    asm("{ .reg .u64 t; cvta.to.shared.u64 t, %1; cvt.u32.u64 %0, t; }" : "=r"(a) : "l"(p));
    return a;
}
__device__ __forceinline__ void ldsm4(uint32_t* r, uint32_t a){
    asm volatile("ldmatrix.sync.aligned.m8n8.x4.shared.b16 {%0,%1,%2,%3}, [%4];"
        : "=r"(r[0]),"=r"(r[1]),"=r"(r[2]),"=r"(r[3]) : "r"(a));
}
__device__ __forceinline__ void ldsm4t(uint32_t* r, uint32_t a){
    asm volatile("ldmatrix.sync.aligned.m8n8.x4.trans.shared.b16 {%0,%1,%2,%3}, [%4];"
        : "=r"(r[0]),"=r"(r[1]),"=r"(r[2]),"=r"(r[3]) : "r"(a));
}
__device__ __forceinline__ void mma16816(float* c, const uint32_t* a, uint32_t b0, uint32_t b1){
    asm volatile("mma.sync.aligned.m16n8k16.row.col.f32.f16.f16.f32 "
        "{%0,%1,%2,%3}, {%4,%5,%6,%7}, {%8,%9}, {%0,%1,%2,%3};"
        : "+f"(c[0]),"+f"(c[1]),"+f"(c[2]),"+f"(c[3])
        : "r"(a[0]),"r"(a[1]),"r"(a[2]),"r"(a[3]), "r"(b0),"r"(b1));
}
__device__ __forceinline__ float ex2f(float x){
    float y; asm("ex2.approx.ftz.f32 %0, %1;" : "=f"(y) : "f"(x)); return y;
}
__device__ __forceinline__ uint32_t pk2h(float a, float b){
    __half2 t = __floats2half2_rn(a, b);
    return *reinterpret_cast<uint32_t*>(&t);
}
__device__ __forceinline__ void split2h(float f0, float f1, uint32_t& h, uint32_t& l){
    __half h0 = __float2half_rn(f0), h1 = __float2half_rn(f1);
    __half2 hh = __halves2half2(h0, h1);
    h = *reinterpret_cast<uint32_t*>(&hh);
    l = pk2h(f0 - __half2float(h0), f1 - __half2float(h1));
}
#define CPA(d,s)   asm volatile("cp.async.cg.shared.global [%0], [%1], 16;" :: "r"((uint32_t)(d)), "l"(s) : "memory")
#define CPCOMMIT() asm volatile("cp.async.commit_group;" ::: "memory")
#define CPWAIT1()  asm volatile("cp.async.wait_group 1;" ::: "memory")
#define CPWAIT0()  asm volatile("cp.async.wait_group 0;" ::: "memory")

// =============================================================================
// input conversion
// =============================================================================
__global__ void split_f32(const float4* __restrict__ src,
                          uint2* __restrict__ hi, uint2* __restrict__ lo, int n4)
{
    int i = blockIdx.x*blockDim.x + threadIdx.x;
    if (i < n4){
        float4 f = src[i];
        uint32_t h0,l0,h1,l1;
        split2h(f.x, f.y, h0, l0);
        split2h(f.z, f.w, h1, l1);
        hi[i] = make_uint2(h0,h1);
        lo[i] = make_uint2(l0,l1);
    }
}
__global__ void conv_f32(const float4* __restrict__ src, uint2* __restrict__ hi, int n4)
{
    int i = blockIdx.x*blockDim.x + threadIdx.x;
    if (i < n4){
        float4 f = src[i];
        hi[i] = make_uint2(pk2h(f.x, f.y), pk2h(f.z, f.w));
    }
}

// =============================================================================
// GEMM tiles: 128x128 CTA, 8 warps (2x4), k-chunk 64, double-buffered cp.async.
// smem per stage: Ahi|Alo|Bhi, each [128][72] fp16 (144B rows, ldsm-clean).
// =============================================================================
#define GPE  72
#define ARR  (128*GPE*2)        /* 18432 B per array */
#define STG  (3*ARR)            /* 55296 B per stage */
#define GEMM_SMEM (2*STG)       /* 110592 B */

__device__ __forceinline__ void gemm_pf(
    uint32_t sb, int s, int c, int row, int half,
    const __half* Ah, const __half* Al, const __half* Bh)
{
    uint32_t base = sb + s*STG + (uint32_t)(row*GPE + half)*2;
    const size_t g = (size_t)c*64 + half;
#pragma unroll
    for (int u = 0; u < 4; u++){
        CPA(base + 0*ARR + u*16, Ah + g + u*8);
        CPA(base + 1*ARR + u*16, Al + g + u*8);
        CPA(base + 2*ARR + u*16, Bh + g + u*8);
    }
}

__device__ __forceinline__ void gemm_compute(
    uint32_t sb, int s, int wm, int wn, int L, float acc[4][4][4])
{
    const uint32_t bA_hi = sb + s*STG, bA_lo = bA_hi + ARR, bB_hi = bA_hi + 2*ARR;
#pragma unroll
    for (int ks = 0; ks < 4; ks++){
        uint32_t ahf[4][4], alf[4][4];
        uint32_t aoff = (uint32_t)(wm + (L & 15))*(GPE*2) + ks*32 + (L >> 4)*16;
#pragma unroll
        for (int im=0; im<4; im++){
            ldsm4(ahf[im], bA_hi + aoff + im*16*(GPE*2));
            ldsm4(alf[im], bA_lo + aoff + im*16*(GPE*2));
        }
        uint32_t bhf[2][4];
        uint32_t boff = (uint32_t)(wn + (L & 7) + ((L>>4)&1)*8)*(GPE*2) + ks*32 + ((L>>3)&1)*16;
#pragma unroll
        for (int jn=0; jn<2; jn++)
            ldsm4(bhf[jn], bB_hi + boff + jn*16*(GPE*2));
#pragma unroll
        for (int im=0; im<4; im++)
#pragma unroll
            for (int n8=0; n8<4; n8++){
                int jn = n8>>1, ss = (n8&1)*2;
                mma16816(acc[im][n8], ahf[im], bhf[jn][ss], bhf[jn][ss+1]);
                mma16816(acc[im][n8], alf[im], bhf[jn][ss], bhf[jn][ss+1]);
            }
    }
}

__global__ __launch_bounds__(256,1)
void qkv_mma()
{
    extern __shared__ __half dsm[];
    const uint32_t sb = smem_u32(dsm);
    const int z = blockIdx.z;
    const __half* Bh = (z==0) ? g_wqhi : (z==1) ? g_wkhi : g_wvhi;

    const int tid = threadIdx.x, L = tid & 31, wid = tid >> 5;
    const int wm = (wid >> 2) * 64, wn = (wid & 3) * 32;
    const int m0 = blockIdx.x * 128, n0 = blockIdx.y * 128;
    const int row = tid >> 1, half = (tid & 1) * 32;

    const __half* Ah = g_xhi + (size_t)(m0+row)*DIM;
    const __half* Al = g_xlo + (size_t)(m0+row)*DIM;
    const __half* Bp = Bh + (size_t)(n0+row)*DIM;

    float acc[4][4][4];
#pragma unroll
    for (int i=0;i<4;i++)
#pragma unroll
        for (int j=0;j<4;j++)
#pragma unroll
            for (int e=0;e<4;e++) acc[i][j][e] = 0.f;

    gemm_pf(sb, 0, 0, row, half, Ah, Al, Bp);
    CPCOMMIT();
    for (int c = 0; c < 12; c++){
        if (c < 11){ gemm_pf(sb, (c+1)&1, c+1, row, half, Ah, Al, Bp); CPCOMMIT(); CPWAIT1(); }
        else CPWAIT0();
        __syncthreads();
        gemm_compute(sb, c&1, wm, wn, L, acc);
        __syncthreads();
    }

    // epilogue: permuted store [b,h,n,d]; q scaled+split, k/v hi-only
    const float qs = (z==0) ? QSCALE : 1.f;
#pragma unroll
    for (int im=0; im<4; im++){
        int r0 = m0 + wm + im*16 + (L>>2);
#pragma unroll
        for (int n8=0; n8<4; n8++){
            int col = n0 + wn + n8*8 + 2*(L&3);
            int head = col >> 6, d = col & 63;
#pragma unroll
            for (int hf2=0; hf2<2; hf2++){
                int m = r0 + hf2*8;
                int b = m >> 12, n = m & (SEQ-1);
                size_t a = ((size_t)(b*NH+head)*SEQ + n)*HD + d;
                float c0 = acc[im][n8][hf2*2], c1 = acc[im][n8][hf2*2+1];
                if (z==0){
                    uint32_t h, l;
                    split2h(c0*qs, c1*qs, h, l);
                    *(uint32_t*)(g_qhi + a) = h;
                    *(uint32_t*)(g_qlo + a) = l;
                } else if (z==1){
                    *(uint32_t*)(g_khi + a) = pk2h(c0, c1);
                } else {
                    *(uint32_t*)(g_vhi + a) = pk2h(c0, c1);
                }
            }
        }
    }
}

__global__ __launch_bounds__(256,1)
void proj_mma(const float* __restrict__ bo, float* __restrict__ out)
{
    extern __shared__ __half dsm[];
    const uint32_t sb = smem_u32(dsm);
    const int tid = threadIdx.x, L = tid & 31, wid = tid >> 5;
    const int wm = (wid >> 2) * 64, wn = (wid & 3) * 32;
    const int m0 = blockIdx.x * 128, n0 = blockIdx.y * 128;
    const int row = tid >> 1, half = (tid & 1) * 32;

    const __half* Ah = g_atthi + (size_t)(m0+row)*DIM;
    const __half* Al = g_attlo + (size_t)(m0+row)*DIM;
    const __half* Bh = g_wohi + (size_t)(n0+row)*DIM;

    float acc[4][4][4];
#pragma unroll
    for (int i=0;i<4;i++)
#pragma unroll
        for (int j=0;j<4;j++)
#pragma unroll
            for (int e=0;e<4;e++) acc[i][j][e] = 0.f;

    gemm_pf(sb, 0, 0, row, half, Ah, Al, Bh);
    CPCOMMIT();
    for (int c = 0; c < 12; c++){
        if (c < 11){ gemm_pf(sb, (c+1)&1, c+1, row, half, Ah, Al, Bh); CPCOMMIT(); CPWAIT1(); }
        else CPWAIT0();
        __syncthreads();
        gemm_compute(sb, c&1, wm, wn, L, acc);
        __syncthreads();
    }

#pragma unroll
    for (int im=0; im<4; im++){
        int r0 = m0 + wm + im*16 + (L>>2);
#pragma unroll
        for (int n8=0; n8<4; n8++){
            int col = n0 + wn + n8*8 + 2*(L&3);
            float b0 = bo[col], b1 = bo[col+1];
            *(float2*)(out + (size_t)r0*DIM + col) =
                make_float2(acc[im][n8][0]+b0, acc[im][n8][1]+b1);
            *(float2*)(out + (size_t)(r0+8)*DIM + col) =
                make_float2(acc[im][n8][2]+b0, acc[im][n8][3]+b1);
        }
    }
}

// =============================================================================
// Attention: CTA = 128 q x 32 KV tiles of 128; double-buffered cp.async KV.
// smem per stage: Khi|Vhi each [128][72] fp16. 2 stages = 73728 B.
// S: Q split (2 MMA), PV: P,V hi-only (1 MMA).
// =============================================================================
#define KVP 72
#define AARR (128*KVP*2)
#define ASTG (2*AARR)
#define ATT_SMEM (2*ASTG)

__device__ __forceinline__ void attn_pf(uint32_t sb, int s, int k0, int row, int half,
                                        size_t base)
{
    uint32_t d = sb + s*ASTG + (uint32_t)(row*KVP + half)*2;
    size_t g = base + (size_t)(k0+row)*HD + half;
#pragma unroll
    for (int u = 0; u < 4; u++){
        CPA(d + 0*AARR + u*16, g_khi + g + u*8);
        CPA(d + 1*AARR + u*16, g_vhi + g + u*8);
    }
}

__global__ __launch_bounds__(256,1)
void attn_mma()
{
    extern __shared__ __half dsm[];
    const uint32_t sb = smem_u32(dsm);
    const int tid = threadIdx.x, L = tid & 31, w = tid >> 5;
    const int bh = blockIdx.x, q0 = blockIdx.y * 128;
    const size_t base = (size_t)bh * SEQ * HD;
    const int row = tid >> 1, half = (tid & 1) * 32;

    // ---- Q tile through stage-0 smem -> A-frags in registers ---------------
    {
        const uint4* qh = (const uint4*)(g_qhi + base + (size_t)(q0+row)*HD + half);
        const uint4* ql = (const uint4*)(g_qlo + base + (size_t)(q0+row)*HD + half);
        uint4* dh = (uint4*)(dsm + row*KVP + half);
        uint4* dl = (uint4*)(dsm + 128*KVP + row*KVP + half);
#pragma unroll
        for (int i=0;i<4;i++){ dh[i] = qh[i]; dl[i] = ql[i]; }
    }
    __syncthreads();
    uint32_t qhf[4][4], qlf[4][4];
    {
        uint32_t aoff = (uint32_t)(w*16 + (L & 15))*(KVP*2) + (L >> 4)*16;
#pragma unroll
        for (int dg=0; dg<4; dg++){
            ldsm4(qhf[dg], sb + aoff + dg*32);
            ldsm4(qlf[dg], sb + AARR + aoff + dg*32);
        }
    }
    __syncthreads();

    float o[8][4];
#pragma unroll
    for (int f=0;f<8;f++)
#pragma unroll
        for (int e=0;e<4;e++) o[f][e] = 0.f;
    float l0 = 0.f, l1 = 0.f;

    attn_pf(sb, 0, 0, row, half, base);
    CPCOMMIT();

    for (int t = 0; t < SEQ/128; t++) {
        if (t < 31){ attn_pf(sb, (t+1)&1, (t+1)*128, row, half, base); CPCOMMIT(); CPWAIT1(); }
        else CPWAIT0();
        __syncthreads();
        const uint32_t sK_hi = sb + (t&1)*ASTG;
        const uint32_t sV_hi = sK_hi + AARR;

        // ---- S = Q K^T (16 x 128 per warp), Q split ------------------------
        float s[16][4];
#pragma unroll
        for (int f=0;f<16;f++)
#pragma unroll
            for (int e=0;e<4;e++) s[f][e] = 0.f;
#pragma unroll
        for (int dg=0; dg<4; dg++){
#pragma unroll
            for (int j=0; j<8; j++){
                uint32_t boff = (uint32_t)(j*16 + (L & 7) + ((L>>4)&1)*8)*(KVP*2)
                              + dg*32 + ((L>>3)&1)*16;
                uint32_t bh4[4];
                ldsm4(bh4, sK_hi + boff);
                mma16816(s[2*j],   qhf[dg], bh4[0], bh4[1]);
                mma16816(s[2*j],   qlf[dg], bh4[0], bh4[1]);
                mma16816(s[2*j+1], qhf[dg], bh4[2], bh4[3]);
                mma16816(s[2*j+1], qlf[dg], bh4[2], bh4[3]);
            }
        }

        // ---- unnormalized exp2 + row-sum ------------------------------------
        float sum0 = 0.f, sum1 = 0.f;
#pragma unroll
        for (int f=0;f<16;f++){
            s[f][0] = ex2f(s[f][0]); s[f][1] = ex2f(s[f][1]);
            s[f][2] = ex2f(s[f][2]); s[f][3] = ex2f(s[f][3]);
            sum0 += s[f][0] + s[f][1];
            sum1 += s[f][2] + s[f][3];
        }
        sum0 += __shfl_xor_sync(0xffffffffu, sum0, 1);
        sum0 += __shfl_xor_sync(0xffffffffu, sum0, 2);
        sum1 += __shfl_xor_sync(0xffffffffu, sum1, 1);
        sum1 += __shfl_xor_sync(0xffffffffu, sum1, 2);
        l0 += sum0; l1 += sum1;

        // ---- O += P V (P,V hi-only: 1 MMA) ----------------------------------
#pragma unroll
        for (int kg=0; kg<8; kg++){
            uint32_t phi[4];
            phi[0] = pk2h(s[2*kg][0],   s[2*kg][1]);
            phi[1] = pk2h(s[2*kg][2],   s[2*kg][3]);
            phi[2] = pk2h(s[2*kg+1][0], s[2*kg+1][1]);
            phi[3] = pk2h(s[2*kg+1][2], s[2*kg+1][3]);
#pragma unroll
            for (int j=0; j<4; j++){
                uint32_t voff = (uint32_t)(kg*16 + (L & 7) + ((L>>3)&1)*8)*(KVP*2)
                              + j*32 + ((L>>4)&1)*16;
                uint32_t vh4[4];
                ldsm4t(vh4, sV_hi + voff);
                mma16816(o[2*j],   phi, vh4[0], vh4[1]);
                mma16816(o[2*j+1], phi, vh4[2], vh4[3]);
            }
        }
        __syncthreads();
    }

    // ---- epilogue: normalize, split, store [b, n, dim] ----------------------
    const int b = bh / NH, head = bh % NH;
    const float inv0 = 1.f / l0, inv1 = 1.f / l1;
    const int r0 = q0 + w*16 + (L>>2);
#pragma unroll
    for (int f=0;f<8;f++){
        int col = f*8 + 2*(L&3);
        size_t a0 = ((size_t)b*SEQ + r0)  *DIM + head*HD + col;
        size_t a1 = ((size_t)b*SEQ + r0+8)*DIM + head*HD + col;
        uint32_t h, l;
        split2h(o[f][0]*inv0, o[f][1]*inv0, h, l);
        *(uint32_t*)(g_atthi + a0) = h; *(uint32_t*)(g_attlo + a0) = l;
        split2h(o[f][2]*inv1, o[f][3]*inv1, h, l);
        *(uint32_t*)(g_atthi + a1) = h; *(uint32_t*)(g_attlo + a1) = l;
    }
}

// -----------------------------------------------------------------------------
extern "C" void kernel_launch(void* const* d_in, const int* in_sizes, int n_in,
                              void* d_out, int out_size)
{
    const float* x  = (const float*)d_in[0];
    const float* wq = (const float*)d_in[1];
    const float* wk = (const float*)d_in[2];
    const float* wv = (const float*)d_in[3];
    const float* wo = (const float*)d_in[4];
    const float* bo = (const float*)d_in[5];
    float* out = (float*)d_out;
    (void)in_sizes; (void)n_in; (void)out_size;

    static __half *xh, *xl, *qh, *kh, *vh, *oh;
    cudaGetSymbolAddress((void**)&xh, g_xhi);  cudaGetSymbolAddress((void**)&xl, g_xlo);
    cudaGetSymbolAddress((void**)&qh, g_wqhi); cudaGetSymbolAddress((void**)&kh, g_wkhi);
    cudaGetSymbolAddress((void**)&vh, g_wvhi); cudaGetSymbolAddress((void**)&oh, g_wohi);

    cudaFuncSetAttribute(qkv_mma,  cudaFuncAttributeMaxDynamicSharedMemorySize, GEMM_SMEM);
    cudaFuncSetAttribute(attn_mma, cudaFuncAttributeMaxDynamicSharedMemorySize, ATT_SMEM);
    cudaFuncSetAttribute(proj_mma, cudaFuncAttributeMaxDynamicSharedMemorySize, GEMM_SMEM);

    const int nx4 = MROWS*DIM/4, nw4 = DIM*DIM/4;
    split_f32<<<(nx4+255)/256, 256>>>((const float4*)x,  (uint2*)xh, (uint2*)xl, nx4);
    conv_f32 <<<(nw4+255)/256, 256>>>((const float4*)wq, (uint2*)qh, nw4);
    conv_f32 <<<(nw4+255)/256, 256>>>((const float4*)wk, (uint2*)kh, nw4);
    conv_f32 <<<(nw4+255)/256, 256>>>((const float4*)wv, (uint2*)vh, nw4);
    conv_f32 <<<(nw4+255)/256, 256>>>((const float4*)wo, (uint2*)oh, nw4);

    qkv_mma <<<dim3(MROWS/128, DIM/128, 3), 256, GEMM_SMEM>>>();
    attn_mma<<<dim3(BHEADS, SEQ/128),       256, ATT_SMEM>>>();
    proj_mma<<<dim3(MROWS/128, DIM/128),    256, GEMM_SMEM>>>(bo, out);
}

// round 8
// speedup vs baseline: 7.2631x; 1.0592x over previous
#include <cuda_runtime.h>
#include <cuda_fp16.h>
#include <math.h>
#include <stdint.h>

#define SEQ    4096
#define DIM    768
#define NH     12
#define HD     64
#define BATCH  2
#define MROWS  (BATCH*SEQ)
#define BHEADS (BATCH*NH)
#define QSCALE 0.18033688011112042f  /* 64^-0.5 * log2(e) */

// fp16 operands: A-side split (hi+lo), B-side hi only
__device__ __half g_xhi[(size_t)MROWS*DIM];
__device__ __half g_xlo[(size_t)MROWS*DIM];
__device__ __half g_wqhi[(size_t)DIM*DIM];
__device__ __half g_wkhi[(size_t)DIM*DIM];
__device__ __half g_wvhi[(size_t)DIM*DIM];
__device__ __half g_wohi[(size_t)DIM*DIM];
__device__ __half g_qhi[(size_t)BHEADS*SEQ*HD];
__device__ __half g_qlo[(size_t)BHEADS*SEQ*HD];
__device__ __half g_khi[(size_t)BHEADS*SEQ*HD];
__device__ __half g_vhi[(size_t)BHEADS*SEQ*HD];
__device__ __half g_atthi[(size_t)MROWS*DIM];
__device__ __half g_attlo[(size_t)MROWS*DIM];

// ---------------- helpers ----------------------------------------------------
__device__ __forceinline__ uint32_t smem_u32(const void* p){
    uint32_t a;
    asm("{ .reg .u64 t; cvta.to.shared.u64 t, %1; cvt.u32.u64 %0, t; }" : "=r"(a) : "l"(p));
    return a;
}
__device__ __forceinline__ void ldsm4(uint32_t* r, uint32_t a){
    asm volatile("ldmatrix.sync.aligned.m8n8.x4.shared.b16 {%0,%1,%2,%3}, [%4];"
        : "=r"(r[0]),"=r"(r[1]),"=r"(r[2]),"=r"(r[3]) : "r"(a));
}
__device__ __forceinline__ void ldsm4t(uint32_t* r, uint32_t a){
    asm volatile("ldmatrix.sync.aligned.m8n8.x4.trans.shared.b16 {%0,%1,%2,%3}, [%4];"
        : "=r"(r[0]),"=r"(r[1]),"=r"(r[2]),"=r"(r[3]) : "r"(a));
}
__device__ __forceinline__ void mma16816(float* c, const uint32_t* a, uint32_t b0, uint32_t b1){
    asm volatile("mma.sync.aligned.m16n8k16.row.col.f32.f16.f16.f32 "
        "{%0,%1,%2,%3}, {%4,%5,%6,%7}, {%8,%9}, {%0,%1,%2,%3};"
        : "+f"(c[0]),"+f"(c[1]),"+f"(c[2]),"+f"(c[3])
        : "r"(a[0]),"r"(a[1]),"r"(a[2]),"r"(a[3]), "r"(b0),"r"(b1));
}
__device__ __forceinline__ uint32_t h2ex2(uint32_t x){
    uint32_t y; asm("ex2.approx.f16x2 %0, %1;" : "=r"(y) : "r"(x)); return y;
}
__device__ __forceinline__ uint32_t pk2h(float a, float b){
    __half2 t = __floats2half2_rn(a, b);
    return *reinterpret_cast<uint32_t*>(&t);
}
__device__ __forceinline__ void split2h(float f0, float f1, uint32_t& h, uint32_t& l){
    __half h0 = __float2half_rn(f0), h1 = __float2half_rn(f1);
    __half2 hh = __halves2half2(h0, h1);
    h = *reinterpret_cast<uint32_t*>(&hh);
    l = pk2h(f0 - __half2float(h0), f1 - __half2float(h1));
}
#define CPA(d,s)   asm volatile("cp.async.cg.shared.global [%0], [%1], 16;" :: "r"((uint32_t)(d)), "l"(s) : "memory")
#define CPCOMMIT() asm volatile("cp.async.commit_group;" ::: "memory")
#define CPWAIT1()  asm volatile("cp.async.wait_group 1;" ::: "memory")
#define CPWAIT0()  asm volatile("cp.async.wait_group 0;" ::: "memory")

// =============================================================================
// input conversion
// =============================================================================
__global__ void split_f32(const float4* __restrict__ src,
                          uint2* __restrict__ hi, uint2* __restrict__ lo, int n4)
{
    int i = blockIdx.x*blockDim.x + threadIdx.x;
    if (i < n4){
        float4 f = src[i];
        uint32_t h0,l0,h1,l1;
        split2h(f.x, f.y, h0, l0);
        split2h(f.z, f.w, h1, l1);
        hi[i] = make_uint2(h0,h1);
        lo[i] = make_uint2(l0,l1);
    }
}
__global__ void conv_w(const float4* __restrict__ wq, const float4* __restrict__ wk,
                       const float4* __restrict__ wv, const float4* __restrict__ wo, int n4)
{
    int i = blockIdx.x*blockDim.x + threadIdx.x;
    if (i >= n4) return;
    const float4* s;
    uint2* d;
    switch (blockIdx.y){
        case 0:  s = wq; d = (uint2*)g_wqhi; break;
        case 1:  s = wk; d = (uint2*)g_wkhi; break;
        case 2:  s = wv; d = (uint2*)g_wvhi; break;
        default: s = wo; d = (uint2*)g_wohi; break;
    }
    float4 f = s[i];
    d[i] = make_uint2(pk2h(f.x, f.y), pk2h(f.z, f.w));
}

// =============================================================================
// GEMM tiles: 128x128 CTA, 8 warps (2x4), k-chunk 64, double-buffered cp.async.
// smem per stage: Ahi|Alo|Bhi, each [128][72] fp16. 2 CTAs/SM.
// =============================================================================
#define GPE  72
#define ARR  (128*GPE*2)        /* 18432 B per array */
#define STG  (3*ARR)            /* 55296 B per stage */
#define GEMM_SMEM (2*STG)       /* 110592 B */

__device__ __forceinline__ void gemm_pf(
    uint32_t sb, int s, int c, int row, int half,
    const __half* Ah, const __half* Al, const __half* Bh)
{
    uint32_t base = sb + s*STG + (uint32_t)(row*GPE + half)*2;
    const size_t g = (size_t)c*64 + half;
#pragma unroll
    for (int u = 0; u < 4; u++){
        CPA(base + 0*ARR + u*16, Ah + g + u*8);
        CPA(base + 1*ARR + u*16, Al + g + u*8);
        CPA(base + 2*ARR + u*16, Bh + g + u*8);
    }
}

__device__ __forceinline__ void gemm_compute(
    uint32_t sb, int s, int wm, int wn, int L, float acc[4][4][4])
{
    const uint32_t bA_hi = sb + s*STG, bA_lo = bA_hi + ARR, bB_hi = bA_hi + 2*ARR;
#pragma unroll
    for (int ks = 0; ks < 4; ks++){
        uint32_t ahf[4][4], alf[4][4];
        uint32_t aoff = (uint32_t)(wm + (L & 15))*(GPE*2) + ks*32 + (L >> 4)*16;
#pragma unroll
        for (int im=0; im<4; im++){
            ldsm4(ahf[im], bA_hi + aoff + im*16*(GPE*2));
            ldsm4(alf[im], bA_lo + aoff + im*16*(GPE*2));
        }
        uint32_t bhf[2][4];
        uint32_t boff = (uint32_t)(wn + (L & 7) + ((L>>4)&1)*8)*(GPE*2) + ks*32 + ((L>>3)&1)*16;
#pragma unroll
        for (int jn=0; jn<2; jn++)
            ldsm4(bhf[jn], bB_hi + boff + jn*16*(GPE*2));
#pragma unroll
        for (int im=0; im<4; im++)
#pragma unroll
            for (int n8=0; n8<4; n8++){
                int jn = n8>>1, ss = (n8&1)*2;
                mma16816(acc[im][n8], ahf[im], bhf[jn][ss], bhf[jn][ss+1]);
                mma16816(acc[im][n8], alf[im], bhf[jn][ss], bhf[jn][ss+1]);
            }
    }
}

__global__ __launch_bounds__(256,2)
void qkv_mma()
{
    extern __shared__ __half dsm[];
    const uint32_t sb = smem_u32(dsm);
    const int z = blockIdx.z;
    const __half* Bh = (z==0) ? g_wqhi : (z==1) ? g_wkhi : g_wvhi;

    const int tid = threadIdx.x, L = tid & 31, wid = tid >> 5;
    const int wm = (wid >> 2) * 64, wn = (wid & 3) * 32;
    const int m0 = blockIdx.x * 128, n0 = blockIdx.y * 128;
    const int row = tid >> 1, half = (tid & 1) * 32;

    const __half* Ah = g_xhi + (size_t)(m0+row)*DIM;
    const __half* Al = g_xlo + (size_t)(m0+row)*DIM;
    const __half* Bp = Bh + (size_t)(n0+row)*DIM;

    float acc[4][4][4];
#pragma unroll
    for (int i=0;i<4;i++)
#pragma unroll
        for (int j=0;j<4;j++)
#pragma unroll
            for (int e=0;e<4;e++) acc[i][j][e] = 0.f;

    gemm_pf(sb, 0, 0, row, half, Ah, Al, Bp);
    CPCOMMIT();
    for (int c = 0; c < 12; c++){
        if (c < 11){ gemm_pf(sb, (c+1)&1, c+1, row, half, Ah, Al, Bp); CPCOMMIT(); CPWAIT1(); }
        else CPWAIT0();
        __syncthreads();
        gemm_compute(sb, c&1, wm, wn, L, acc);
        __syncthreads();
    }

    const float qs = (z==0) ? QSCALE : 1.f;
#pragma unroll
    for (int im=0; im<4; im++){
        int r0 = m0 + wm + im*16 + (L>>2);
#pragma unroll
        for (int n8=0; n8<4; n8++){
            int col = n0 + wn + n8*8 + 2*(L&3);
            int head = col >> 6, d = col & 63;
#pragma unroll
            for (int hf2=0; hf2<2; hf2++){
                int m = r0 + hf2*8;
                int b = m >> 12, n = m & (SEQ-1);
                size_t a = ((size_t)(b*NH+head)*SEQ + n)*HD + d;
                float c0 = acc[im][n8][hf2*2], c1 = acc[im][n8][hf2*2+1];
                if (z==0){
                    uint32_t h, l;
                    split2h(c0*qs, c1*qs, h, l);
                    *(uint32_t*)(g_qhi + a) = h;
                    *(uint32_t*)(g_qlo + a) = l;
                } else if (z==1){
                    *(uint32_t*)(g_khi + a) = pk2h(c0, c1);
                } else {
                    *(uint32_t*)(g_vhi + a) = pk2h(c0, c1);
                }
            }
        }
    }
}

__global__ __launch_bounds__(256,2)
void proj_mma(const float* __restrict__ bo, float* __restrict__ out)
{
    extern __shared__ __half dsm[];
    const uint32_t sb = smem_u32(dsm);
    const int tid = threadIdx.x, L = tid & 31, wid = tid >> 5;
    const int wm = (wid >> 2) * 64, wn = (wid & 3) * 32;
    const int m0 = blockIdx.x * 128, n0 = blockIdx.y * 128;
    const int row = tid >> 1, half = (tid & 1) * 32;

    const __half* Ah = g_atthi + (size_t)(m0+row)*DIM;
    const __half* Al = g_attlo + (size_t)(m0+row)*DIM;
    const __half* Bh = g_wohi + (size_t)(n0+row)*DIM;

    float acc[4][4][4];
#pragma unroll
    for (int i=0;i<4;i++)
#pragma unroll
        for (int j=0;j<4;j++)
#pragma unroll
            for (int e=0;e<4;e++) acc[i][j][e] = 0.f;

    gemm_pf(sb, 0, 0, row, half, Ah, Al, Bh);
    CPCOMMIT();
    for (int c = 0; c < 12; c++){
        if (c < 11){ gemm_pf(sb, (c+1)&1, c+1, row, half, Ah, Al, Bh); CPCOMMIT(); CPWAIT1(); }
        else CPWAIT0();
        __syncthreads();
        gemm_compute(sb, c&1, wm, wn, L, acc);
        __syncthreads();
    }

#pragma unroll
    for (int im=0; im<4; im++){
        int r0 = m0 + wm + im*16 + (L>>2);
#pragma unroll
        for (int n8=0; n8<4; n8++){
            int col = n0 + wn + n8*8 + 2*(L&3);
            float b0 = bo[col], b1 = bo[col+1];
            *(float2*)(out + (size_t)r0*DIM + col) =
                make_float2(acc[im][n8][0]+b0, acc[im][n8][1]+b1);
            *(float2*)(out + (size_t)(r0+8)*DIM + col) =
                make_float2(acc[im][n8][2]+b0, acc[im][n8][3]+b1);
        }
    }
}

// =============================================================================
// Attention: CTA = 128 q x 32 KV tiles of 128; 2 CTAs/SM.
// KV double-buffered (2 stages of K|V) + persistent Q (hi|lo) region.
// Per tile: two 64-kv-col halves; S = Q-split (2 MMA), exp2.f16x2,
// PV hi-only + ones-column MMA for row sums.
// =============================================================================
#define KVP  72
#define AARR (128*KVP*2)        /* 18432 */
#define ASTG (2*AARR)           /* K|V per stage: 36864 */
#define AQOFF (2*ASTG)          /* 73728 */
#define ATT_SMEM (2*ASTG + 2*AARR)   /* 110592 */

__device__ __forceinline__ void attn_pf(uint32_t sb, int s, int k0, int row, int half,
                                        size_t base)
{
    uint32_t d = sb + s*ASTG + (uint32_t)(row*KVP + half)*2;
    size_t g = base + (size_t)(k0+row)*HD + half;
#pragma unroll
    for (int u = 0; u < 4; u++){
        CPA(d + 0*AARR + u*16, g_khi + g + u*8);
        CPA(d + 1*AARR + u*16, g_vhi + g + u*8);
    }
}

__global__ __launch_bounds__(256,2)
void attn_mma()
{
    extern __shared__ __half dsm[];
    const uint32_t sb = smem_u32(dsm);
    const int tid = threadIdx.x, L = tid & 31, w = tid >> 5;
    const int bh = blockIdx.x, q0 = blockIdx.y * 128;
    const size_t base = (size_t)bh * SEQ * HD;
    const int row = tid >> 1, half = (tid & 1) * 32;

    // Q tile -> persistent smem region (visible after first in-loop sync)
    {
        const uint4* qh = (const uint4*)(g_qhi + base + (size_t)(q0+row)*HD + half);
        const uint4* ql = (const uint4*)(g_qlo + base + (size_t)(q0+row)*HD + half);
        uint4* dh = (uint4*)(dsm + AQOFF/2 + row*KVP + half);
        uint4* dl = (uint4*)(dsm + AQOFF/2 + AARR/2 + row*KVP + half);
#pragma unroll
        for (int i=0;i<4;i++){ dh[i] = qh[i]; dl[i] = ql[i]; }
    }

    float o[8][4], osum[4];
#pragma unroll
    for (int f=0;f<8;f++)
#pragma unroll
        for (int e=0;e<4;e++) o[f][e] = 0.f;
#pragma unroll
    for (int e=0;e<4;e++) osum[e] = 0.f;

    const uint32_t ones = ((L>>2)==0) ? 0x3C003C00u : 0u;   // B-frag: col 0 = 1.0
    const uint32_t sQh = sb + AQOFF, sQl = sQh + AARR;
    const uint32_t aoff = (uint32_t)(w*16 + (L&15))*(KVP*2) + (L>>4)*16;

    attn_pf(sb, 0, 0, row, half, base);
    CPCOMMIT();

    for (int t = 0; t < SEQ/128; t++) {
        if (t < 31){ attn_pf(sb, (t+1)&1, (t+1)*128, row, half, base); CPCOMMIT(); CPWAIT1(); }
        else CPWAIT0();
        __syncthreads();
        const uint32_t sK = sb + (t&1)*ASTG;
        const uint32_t sV = sK + AARR;

#pragma unroll
        for (int h = 0; h < 2; h++){
            // ---- S = Q K^T over 64 kv cols, Q split -------------------------
            float s[8][4];
#pragma unroll
            for (int f=0;f<8;f++)
#pragma unroll
                for (int e=0;e<4;e++) s[f][e] = 0.f;
#pragma unroll
            for (int dg=0; dg<4; dg++){
                uint32_t qh4[4], ql4[4];
                ldsm4(qh4, sQh + aoff + dg*32);
                ldsm4(ql4, sQl + aoff + dg*32);
#pragma unroll
                for (int j=0; j<4; j++){
                    int jj = h*4 + j;
                    uint32_t boff = (uint32_t)(jj*16 + (L & 7) + ((L>>4)&1)*8)*(KVP*2)
                                  + dg*32 + ((L>>3)&1)*16;
                    uint32_t bh4[4];
                    ldsm4(bh4, sK + boff);
                    mma16816(s[2*j],   qh4, bh4[0], bh4[1]);
                    mma16816(s[2*j],   ql4, bh4[0], bh4[1]);
                    mma16816(s[2*j+1], qh4, bh4[2], bh4[3]);
                    mma16816(s[2*j+1], ql4, bh4[2], bh4[3]);
                }
            }

            // ---- P = exp2(S) in fp16x2 --------------------------------------
            uint32_t phi[4][4];
#pragma unroll
            for (int kg=0; kg<4; kg++){
                phi[kg][0] = h2ex2(pk2h(s[2*kg][0],   s[2*kg][1]));
                phi[kg][1] = h2ex2(pk2h(s[2*kg][2],   s[2*kg][3]));
                phi[kg][2] = h2ex2(pk2h(s[2*kg+1][0], s[2*kg+1][1]));
                phi[kg][3] = h2ex2(pk2h(s[2*kg+1][2], s[2*kg+1][3]));
            }

            // ---- O += P V ; osum += P ones ----------------------------------
#pragma unroll
            for (int kg=0; kg<4; kg++){
#pragma unroll
                for (int j=0; j<4; j++){
                    uint32_t voff = (uint32_t)(h*64 + kg*16 + (L & 7) + ((L>>3)&1)*8)*(KVP*2)
                                  + j*32 + ((L>>4)&1)*16;
                    uint32_t vh4[4];
                    ldsm4t(vh4, sV + voff);
                    mma16816(o[2*j],   phi[kg], vh4[0], vh4[1]);
                    mma16816(o[2*j+1], phi[kg], vh4[2], vh4[3]);
                }
                mma16816(osum, phi[kg], ones, ones);
            }
        }
        __syncthreads();
    }

    // ---- epilogue: l from osum col 0, normalize, split, store [b, n, dim] ---
    const int b = bh / NH, head = bh % NH;
    const float ls0 = __shfl_sync(0xffffffffu, osum[0], L & 0x1C);
    const float ls1 = __shfl_sync(0xffffffffu, osum[2], L & 0x1C);
    const float inv0 = 1.f / ls0, inv1 = 1.f / ls1;
    const int r0 = q0 + w*16 + (L>>2);
#pragma unroll
    for (int f=0;f<8;f++){
        int col = f*8 + 2*(L&3);
        size_t a0 = ((size_t)b*SEQ + r0)  *DIM + head*HD + col;
        size_t a1 = ((size_t)b*SEQ + r0+8)*DIM + head*HD + col;
        uint32_t h, l;
        split2h(o[f][0]*inv0, o[f][1]*inv0, h, l);
        *(uint32_t*)(g_atthi + a0) = h; *(uint32_t*)(g_attlo + a0) = l;
        split2h(o[f][2]*inv1, o[f][3]*inv1, h, l);
        *(uint32_t*)(g_atthi + a1) = h; *(uint32_t*)(g_attlo + a1) = l;
    }
}

// -----------------------------------------------------------------------------
extern "C" void kernel_launch(void* const* d_in, const int* in_sizes, int n_in,
                              void* d_out, int out_size)
{
    const float* x  = (const float*)d_in[0];
    const float* wq = (const float*)d_in[1];
    const float* wk = (const float*)d_in[2];
    const float* wv = (const float*)d_in[3];
    const float* wo = (const float*)d_in[4];
    const float* bo = (const float*)d_in[5];
    float* out = (float*)d_out;
    (void)in_sizes; (void)n_in; (void)out_size;

    static __half *xh, *xl;
    cudaGetSymbolAddress((void**)&xh, g_xhi);
    cudaGetSymbolAddress((void**)&xl, g_xlo);

    cudaFuncSetAttribute(qkv_mma,  cudaFuncAttributeMaxDynamicSharedMemorySize, GEMM_SMEM);
    cudaFuncSetAttribute(attn_mma, cudaFuncAttributeMaxDynamicSharedMemorySize, ATT_SMEM);
    cudaFuncSetAttribute(proj_mma, cudaFuncAttributeMaxDynamicSharedMemorySize, GEMM_SMEM);

    const int nx4 = MROWS*DIM/4, nw4 = DIM*DIM/4;
    split_f32<<<(nx4+255)/256, 256>>>((const float4*)x, (uint2*)xh, (uint2*)xl, nx4);
    conv_w<<<dim3((nw4+255)/256, 4), 256>>>((const float4*)wq, (const float4*)wk,
                                            (const float4*)wv, (const float4*)wo, nw4);

    qkv_mma <<<dim3(MROWS/128, DIM/128, 3), 256, GEMM_SMEM>>>();
    attn_mma<<<dim3(BHEADS, SEQ/128),       256, ATT_SMEM>>>();
    proj_mma<<<dim3(MROWS/128, DIM/128),    256, GEMM_SMEM>>>(bo, out);
}